// round 4
// baseline (speedup 1.0000x reference)
#include <cuda_runtime.h>
#include <math.h>

#define N_NODES 50000
#define N_EDGES 400000
#define ET (N_EDGES + N_NODES)   // 450000 edges incl. self-loops
#define TB 256

// ---------------- scratch (device globals; no allocs allowed) ----------------
__device__ float g_xl [(size_t)N_NODES * 768];   // per-conv transformed features
__device__ float g_x1 [(size_t)N_NODES * 256];
__device__ float g_x2 [(size_t)N_NODES * 256];
__device__ float g_x3 [(size_t)N_NODES * 768];
__device__ float g_gg [(size_t)N_NODES * 32];
__device__ float g_t32[(size_t)N_NODES * 32];
__device__ float g_xa1[(size_t)N_NODES * 80];
__device__ float g_xa2[(size_t)N_NODES * 200];
__device__ float g_xf0[(size_t)N_NODES * 1080];
__device__ float g_xf1[(size_t)N_NODES * 200];
__device__ float g_xf2[(size_t)N_NODES * 64];
__device__ float g_als[(size_t)N_NODES * 12];
__device__ float g_ald[(size_t)N_NODES * 12];
__device__ float g_m  [(size_t)N_NODES * 12];
__device__ float g_den[(size_t)N_NODES * 12];
__device__ float g_ex [(size_t)ET * 12];
__device__ int   g_src[ET];
__device__ int   g_dst[ET];
__device__ int   g_is64;          // 1 if edge_index delivered as int64

// ---------------- dtype probe: int64 little-endian => odd int32 words all 0 ---
__global__ void detect_dtype_k(const int* __restrict__ ei32) {
    // values are in [0, 50000) so int64 high words are 0; int32 edge data at
    // odd positions is ~Uniform[0,50000) -> P(16 zeros) ~ 0.
    int all_zero = 1;
#pragma unroll
    for (int i = 0; i < 16; i++)
        if (ei32[2 * i + 1] != 0) all_zero = 0;
    g_is64 = all_zero;
}

// ---------------- edge prep: decode per detected dtype + self loops -----------
__global__ void prep_edges_k(const void* __restrict__ ei) {
    int i = blockIdx.x * blockDim.x + threadIdx.x;
    if (i >= ET) return;
    if (i < N_EDGES) {
        if (g_is64) {
            const long long* p = (const long long*)ei;
            g_src[i] = (int)p[i];
            g_dst[i] = (int)p[N_EDGES + i];
        } else {
            const int* p = (const int*)ei;
            g_src[i] = p[i];
            g_dst[i] = p[N_EDGES + i];
        }
    } else {
        int v = i - N_EDGES;
        g_src[i] = v;
        g_dst[i] = v;
    }
}

// ---------------- generic tiled fp32 GEMM: C = act(A[N,M]@B[M,K] + bias) ------
// BM=BN=64, BK=16, 256 threads, 4x4 per thread
__global__ void gemm_k(const float* __restrict__ A, const float* __restrict__ B,
                       const float* __restrict__ bias, float* __restrict__ C,
                       int Nr, int M, int K, int act) {
    __shared__ float As[16][64];
    __shared__ float Bs[16][64];
    int tx = threadIdx.x % 16;        // col group
    int ty = threadIdx.x / 16;        // row group
    int rowBase = blockIdx.y * 64;
    int colBase = blockIdx.x * 64;
    float acc[4][4] = {};
    for (int k0 = 0; k0 < M; k0 += 16) {
        for (int i = threadIdx.x; i < 64 * 16; i += 256) {
            int m = i >> 4, k = i & 15;
            int r = rowBase + m, kk = k0 + k;
            As[k][m] = (r < Nr && kk < M) ? A[(size_t)r * M + kk] : 0.f;
        }
        for (int i = threadIdx.x; i < 16 * 64; i += 256) {
            int k = i >> 6, n = i & 63;
            int kk = k0 + k, c = colBase + n;
            Bs[k][n] = (kk < M && c < K) ? B[(size_t)kk * K + c] : 0.f;
        }
        __syncthreads();
#pragma unroll
        for (int k = 0; k < 16; k++) {
            float a[4], b[4];
#pragma unroll
            for (int i = 0; i < 4; i++) a[i] = As[k][ty * 4 + i];
#pragma unroll
            for (int j = 0; j < 4; j++) b[j] = Bs[k][tx * 4 + j];
#pragma unroll
            for (int i = 0; i < 4; i++)
#pragma unroll
                for (int j = 0; j < 4; j++) acc[i][j] += a[i] * b[j];
        }
        __syncthreads();
    }
#pragma unroll
    for (int i = 0; i < 4; i++) {
        int r = rowBase + ty * 4 + i;
        if (r >= Nr) continue;
#pragma unroll
        for (int j = 0; j < 4; j++) {
            int c = colBase + tx * 4 + j;
            if (c >= K) continue;
            float v = acc[i][j] + (bias ? bias[c] : 0.f);
            if (act) v = fmaxf(v, 0.f);
            C[(size_t)r * K + c] = v;
        }
    }
}

// ---------------- per-node attention logits: warp per (n,h) -------------------
template <int H, int C>
__global__ void alpha_k(const float* __restrict__ xl,
                        const float* __restrict__ a_src,
                        const float* __restrict__ a_dst) {
    int gw = (blockIdx.x * blockDim.x + threadIdx.x) >> 5;
    int lane = threadIdx.x & 31;
    if (gw >= N_NODES * H) return;
    int n = gw / H, h = gw - n * H;
    const float* row = xl + (size_t)n * (H * C) + h * C;
    float s1 = 0.f, s2 = 0.f;
#pragma unroll
    for (int c = lane; c < C; c += 32) {
        float v = row[c];
        s1 += v * a_src[h * C + c];
        s2 += v * a_dst[h * C + c];
    }
#pragma unroll
    for (int o = 16; o; o >>= 1) {
        s1 += __shfl_down_sync(0xffffffffu, s1, o);
        s2 += __shfl_down_sync(0xffffffffu, s2, o);
    }
    if (lane == 0) { g_als[gw] = s1; g_ald[gw] = s2; }
}

// ---------------- init m/den and zero out-accumulator -------------------------
__global__ void init_conv_k(float* __restrict__ out, int H, int HC) {
    int i = blockIdx.x * blockDim.x + threadIdx.x;
    if (i < N_NODES * H) { g_m[i] = -1e30f; g_den[i] = 0.f; }
    if (i < N_NODES * HC) out[i] = 0.f;
}

__device__ __forceinline__ float lrelu(float v) { return v > 0.f ? v : 0.2f * v; }

__device__ __forceinline__ void atomicMaxF(float* addr, float val) {
    int old = __float_as_int(*addr);
    while (__int_as_float(old) < val) {
        int assumed = old;
        old = atomicCAS((int*)addr, assumed, __float_as_int(val));
        if (old == assumed) break;
    }
}

// ---------------- edge pass 1: segment max ------------------------------------
template <int H>
__global__ void edge_max_k() {
    int i = blockIdx.x * blockDim.x + threadIdx.x;
    if (i >= ET * H) return;
    int e = i / H, h = i - e * H;
    int s = g_src[e], d = g_dst[e];
    float v = lrelu(g_als[s * H + h] + g_ald[d * H + h]);
    atomicMaxF(&g_m[d * H + h], v);
}

// ---------------- edge pass 2: exp + segment sum ------------------------------
template <int H>
__global__ void edge_exp_k() {
    int i = blockIdx.x * blockDim.x + threadIdx.x;
    if (i >= ET * H) return;
    int e = i / H, h = i - e * H;
    int s = g_src[e], d = g_dst[e];
    float v = lrelu(g_als[s * H + h] + g_ald[d * H + h]);
    float ex = __expf(v - g_m[d * H + h]);
    g_ex[i] = ex;
    atomicAdd(&g_den[d * H + h], ex);
}

// ---------------- edge pass 3: weighted scatter (warp per edge) ---------------
template <int H, int C>
__global__ void edge_agg_k(const float* __restrict__ xl, float* __restrict__ out) {
    int w = (blockIdx.x * blockDim.x + threadIdx.x) >> 5;
    int lane = threadIdx.x & 31;
    if (w >= ET) return;
    int s = g_src[w], d = g_dst[w];
    float coef[H];
#pragma unroll
    for (int h = 0; h < H; h++)
        coef[h] = g_ex[(size_t)w * H + h] / g_den[(size_t)d * H + h];
    const float* xr = xl + (size_t)s * (H * C);
    float* orow = out + (size_t)d * (H * C);
#pragma unroll
    for (int k = 0; k < (H * C) / 32; k++) {
        int j = lane + k * 32;
        const int h = (k * 32) / C;           // compile-time per unrolled iter
        atomicAdd(&orow[j], coef[h] * xr[j]);
    }
}

// ---------------- bias + relu epilogue ----------------------------------------
__global__ void bias_relu_k(float* __restrict__ x, const float* __restrict__ b,
                            int K, int total) {
    int i = blockIdx.x * blockDim.x + threadIdx.x;
    if (i >= total) return;
    x[i] = fmaxf(x[i] + b[i % K], 0.f);
}

// ---------------- concat [gg | x3 | xa1 | xa2] -> xf0 [N,1080] ----------------
__global__ void concat_k() {
    int i = blockIdx.x * blockDim.x + threadIdx.x;
    if (i >= N_NODES * 1080) return;
    int n = i / 1080, j = i - n * 1080;
    float v;
    if (j < 32)       v = g_gg[n * 32 + j];
    else if (j < 800) v = g_x3[(size_t)n * 768 + (j - 32)];
    else if (j < 880) v = g_xa1[n * 80 + (j - 800)];
    else              v = g_xa2[n * 200 + (j - 880)];
    g_xf0[(size_t)i] = v;
}

// ---------------- final: sigmoid(dot(xf2[n,:64], w) + b) ----------------------
__global__ void final_k(const float* __restrict__ xf2, const float* __restrict__ w,
                        const float* __restrict__ b, float* __restrict__ out) {
    int gw = (blockIdx.x * blockDim.x + threadIdx.x) >> 5;
    int lane = threadIdx.x & 31;
    if (gw >= N_NODES) return;
    const float* r = xf2 + (size_t)gw * 64;
    float s = r[lane] * w[lane] + r[lane + 32] * w[lane + 32];
#pragma unroll
    for (int o = 16; o; o >>= 1) s += __shfl_down_sync(0xffffffffu, s, o);
    if (lane == 0) out[gw] = 1.f / (1.f + expf(-(s + b[0])));
}

// =============================================================================
static inline dim3 gemm_grid(int K) { return dim3((K + 63) / 64, (N_NODES + 63) / 64); }
static inline int cdiv(int a, int b) { return (a + b - 1) / b; }

extern "C" void kernel_launch(void* const* d_in, const int* in_sizes, int n_in,
                              void* d_out, int out_size) {
    const float* x  = (const float*)d_in[0];
    const void*  ei = d_in[1];                     // dtype auto-detected on device
    const float *W1 = (const float*)d_in[2],  *as1 = (const float*)d_in[3],
                *ad1 = (const float*)d_in[4], *b1  = (const float*)d_in[5];
    const float *W2 = (const float*)d_in[6],  *as2 = (const float*)d_in[7],
                *ad2 = (const float*)d_in[8], *b2  = (const float*)d_in[9];
    const float *W3 = (const float*)d_in[10], *as3 = (const float*)d_in[11],
                *ad3 = (const float*)d_in[12], *b3 = (const float*)d_in[13];
    const float *ln1_w = (const float*)d_in[14], *ln1_b = (const float*)d_in[15];
    const float *ln2_w = (const float*)d_in[16], *ln2_b = (const float*)d_in[17];
    const float *la1_w = (const float*)d_in[18], *la1_b = (const float*)d_in[19];
    const float *la3_w = (const float*)d_in[20], *la3_b = (const float*)d_in[21];
    const float *lf1_w = (const float*)d_in[22], *lf1_b = (const float*)d_in[23];
    const float *lf2_w = (const float*)d_in[24], *lf2_b = (const float*)d_in[25];
    const float *lf3_w = (const float*)d_in[26], *lf3_b = (const float*)d_in[27];
    float* out = (float*)d_out;

    float *xl, *x1, *x2, *x3, *gg, *t32, *xa1, *xa2, *xf0, *xf1, *xf2;
    cudaGetSymbolAddress((void**)&xl,  g_xl);
    cudaGetSymbolAddress((void**)&x1,  g_x1);
    cudaGetSymbolAddress((void**)&x2,  g_x2);
    cudaGetSymbolAddress((void**)&x3,  g_x3);
    cudaGetSymbolAddress((void**)&gg,  g_gg);
    cudaGetSymbolAddress((void**)&t32, g_t32);
    cudaGetSymbolAddress((void**)&xa1, g_xa1);
    cudaGetSymbolAddress((void**)&xa2, g_xa2);
    cudaGetSymbolAddress((void**)&xf0, g_xf0);
    cudaGetSymbolAddress((void**)&xf1, g_xf1);
    cudaGetSymbolAddress((void**)&xf2, g_xf2);

    detect_dtype_k<<<1, 1>>>((const int*)ei);
    prep_edges_k<<<cdiv(ET, TB), TB>>>(ei);

    // dense gg path
    gemm_k<<<gemm_grid(32), TB>>>(x,   ln1_w, ln1_b, t32, N_NODES, 16, 32, 1);
    gemm_k<<<gemm_grid(32), TB>>>(t32, ln2_w, ln2_b, gg,  N_NODES, 32, 32, 1);

    // ---- conv1: 16 -> 8x32 ----
    {
        const int H = 8, C = 32, HC = 256;
        gemm_k<<<gemm_grid(HC), TB>>>(x, W1, nullptr, xl, N_NODES, 16, HC, 0);
        alpha_k<H, C><<<cdiv(N_NODES * H * 32, TB), TB>>>(xl, as1, ad1);
        init_conv_k<<<cdiv(N_NODES * HC, TB), TB>>>(x1, H, HC);
        edge_max_k<H><<<cdiv(ET * H, TB), TB>>>();
        edge_exp_k<H><<<cdiv(ET * H, TB), TB>>>();
        edge_agg_k<H, C><<<cdiv(ET * 32, TB), TB>>>(xl, x1);
        bias_relu_k<<<cdiv(N_NODES * HC, TB), TB>>>(x1, b1, HC, N_NODES * HC);
    }
    // ---- conv2: 256 -> 8x32 ----
    {
        const int H = 8, C = 32, HC = 256;
        gemm_k<<<gemm_grid(HC), TB>>>(x1, W2, nullptr, xl, N_NODES, 256, HC, 0);
        alpha_k<H, C><<<cdiv(N_NODES * H * 32, TB), TB>>>(xl, as2, ad2);
        init_conv_k<<<cdiv(N_NODES * HC, TB), TB>>>(x2, H, HC);
        edge_max_k<H><<<cdiv(ET * H, TB), TB>>>();
        edge_exp_k<H><<<cdiv(ET * H, TB), TB>>>();
        edge_agg_k<H, C><<<cdiv(ET * 32, TB), TB>>>(xl, x2);
        bias_relu_k<<<cdiv(N_NODES * HC, TB), TB>>>(x2, b2, HC, N_NODES * HC);
    }
    // ---- conv3: 256 -> 12x64 ----
    {
        const int H = 12, C = 64, HC = 768;
        gemm_k<<<gemm_grid(HC), TB>>>(x2, W3, nullptr, xl, N_NODES, 256, HC, 0);
        alpha_k<H, C><<<cdiv(N_NODES * H * 32, TB), TB>>>(xl, as3, ad3);
        init_conv_k<<<cdiv(N_NODES * HC, TB), TB>>>(x3, H, HC);
        edge_max_k<H><<<cdiv(ET * H, TB), TB>>>();
        edge_exp_k<H><<<cdiv(ET * H, TB), TB>>>();
        edge_agg_k<H, C><<<cdiv(ET * 32, TB), TB>>>(xl, x3);
        bias_relu_k<<<cdiv(N_NODES * HC, TB), TB>>>(x3, b3, HC, N_NODES * HC);
    }

    // side dense paths
    gemm_k<<<gemm_grid(80),  TB>>>(x1, la1_w, la1_b, xa1, N_NODES, 256, 80, 1);
    gemm_k<<<gemm_grid(200), TB>>>(x2, la3_w, la3_b, xa2, N_NODES, 256, 200, 1);

    // concat + MLP head
    concat_k<<<cdiv(N_NODES * 1080, TB), TB>>>();
    gemm_k<<<gemm_grid(200), TB>>>(xf0, lf1_w, lf1_b, xf1, N_NODES, 1080, 200, 1);
    gemm_k<<<gemm_grid(64),  TB>>>(xf1, lf2_w, lf2_b, xf2, N_NODES, 200, 64, 1);
    final_k<<<cdiv(N_NODES * 32, TB), TB>>>(xf2, lf3_w, lf3_b, out);
}

// round 5
// speedup vs baseline: 1.1603x; 1.1603x over previous
#include <cuda_runtime.h>
#include <math.h>

#define N_NODES 50000
#define N_EDGES 400000
#define ET (N_EDGES + N_NODES)   // 450000 edges incl. self-loops
#define TB 256

// ---------------- scratch (device globals; no allocs allowed) ----------------
__device__ float g_xl [(size_t)N_NODES * 768];   // per-conv transformed features
__device__ float g_x1 [(size_t)N_NODES * 256];
__device__ float g_x2 [(size_t)N_NODES * 256];
__device__ float g_t32[(size_t)N_NODES * 32];
__device__ float g_xf0[(size_t)N_NODES * 1080];  // [gg | conv3 | xa1 | xa2]
__device__ float g_xf1[(size_t)N_NODES * 200];
__device__ float g_xf2[(size_t)N_NODES * 64];
__device__ float g_als[(size_t)N_NODES * 12];
__device__ float g_ald[(size_t)N_NODES * 12];
__device__ int   g_src[ET];
__device__ int   g_dst[ET];
__device__ int   g_deg[N_NODES];
__device__ int   g_rs [N_NODES + 1];   // CSR row starts (by dst)
__device__ int   g_cur[N_NODES];       // scatter cursors
__device__ int   g_csr[ET];            // src node per CSR slot
__device__ int   g_is64;

// ---------------- dtype probe: int64 little-endian => odd int32 words all 0 ---
__global__ void detect_dtype_k(const int* __restrict__ ei32) {
    int all_zero = 1;
#pragma unroll
    for (int i = 0; i < 16; i++)
        if (ei32[2 * i + 1] != 0) all_zero = 0;
    g_is64 = all_zero;
}

__global__ void zero_deg_k() {
    int i = blockIdx.x * blockDim.x + threadIdx.x;
    if (i < N_NODES) g_deg[i] = 0;
}

// ---------------- edge prep: decode + self loops + degree histogram -----------
__global__ void prep_edges_k(const void* __restrict__ ei) {
    int i = blockIdx.x * blockDim.x + threadIdx.x;
    if (i >= ET) return;
    int s, d;
    if (i < N_EDGES) {
        if (g_is64) {
            const long long* p = (const long long*)ei;
            s = (int)p[i]; d = (int)p[N_EDGES + i];
        } else {
            const int* p = (const int*)ei;
            s = p[i]; d = p[N_EDGES + i];
        }
    } else {
        s = d = i - N_EDGES;
    }
    g_src[i] = s;
    g_dst[i] = d;
    atomicAdd(&g_deg[d], 1);
}

// ---------------- single-block scan: deg -> row starts + cursors --------------
__global__ void scan_k() {
    const int T = 1024, CH = (N_NODES + T - 1) / T;   // 49
    __shared__ int sh[T];
    int t = threadIdx.x;
    int base = t * CH;
    int sum = 0;
    for (int i = 0; i < CH; i++) {
        int idx = base + i;
        if (idx < N_NODES) sum += g_deg[idx];
    }
    sh[t] = sum;
    __syncthreads();
    for (int o = 1; o < T; o <<= 1) {
        int v = (t >= o) ? sh[t - o] : 0;
        __syncthreads();
        sh[t] += v;
        __syncthreads();
    }
    int run = (t == 0) ? 0 : sh[t - 1];
    for (int i = 0; i < CH; i++) {
        int idx = base + i;
        if (idx < N_NODES) {
            g_rs[idx] = run;
            g_cur[idx] = run;
            run += g_deg[idx];
        }
    }
    if (t == T - 1) g_rs[N_NODES] = run;   // == ET
}

__global__ void scatter_k() {
    int e = blockIdx.x * blockDim.x + threadIdx.x;
    if (e >= ET) return;
    int pos = atomicAdd(&g_cur[g_dst[e]], 1);
    g_csr[pos] = g_src[e];
}

// ---------------- tiled fp32 GEMM: C[:,off:off+K] = act(A@B + bias) -----------
__global__ void gemm_k(const float* __restrict__ A, const float* __restrict__ B,
                       const float* __restrict__ bias, float* __restrict__ C,
                       int Nr, int M, int K, int act, int ldC, int colOff) {
    __shared__ float As[16][64];
    __shared__ float Bs[16][64];
    int tx = threadIdx.x % 16;
    int ty = threadIdx.x / 16;
    int rowBase = blockIdx.y * 64;
    int colBase = blockIdx.x * 64;
    float acc[4][4] = {};
    for (int k0 = 0; k0 < M; k0 += 16) {
        for (int i = threadIdx.x; i < 64 * 16; i += 256) {
            int m = i >> 4, k = i & 15;
            int r = rowBase + m, kk = k0 + k;
            As[k][m] = (r < Nr && kk < M) ? A[(size_t)r * M + kk] : 0.f;
        }
        for (int i = threadIdx.x; i < 16 * 64; i += 256) {
            int k = i >> 6, n = i & 63;
            int kk = k0 + k, c = colBase + n;
            Bs[k][n] = (kk < M && c < K) ? B[(size_t)kk * K + c] : 0.f;
        }
        __syncthreads();
#pragma unroll
        for (int k = 0; k < 16; k++) {
            float a[4], b[4];
#pragma unroll
            for (int i = 0; i < 4; i++) a[i] = As[k][ty * 4 + i];
#pragma unroll
            for (int j = 0; j < 4; j++) b[j] = Bs[k][tx * 4 + j];
#pragma unroll
            for (int i = 0; i < 4; i++)
#pragma unroll
                for (int j = 0; j < 4; j++) acc[i][j] += a[i] * b[j];
        }
        __syncthreads();
    }
#pragma unroll
    for (int i = 0; i < 4; i++) {
        int r = rowBase + ty * 4 + i;
        if (r >= Nr) continue;
#pragma unroll
        for (int j = 0; j < 4; j++) {
            int c = colBase + tx * 4 + j;
            if (c >= K) continue;
            float v = acc[i][j] + (bias ? bias[c] : 0.f);
            if (act) v = fmaxf(v, 0.f);
            C[(size_t)r * ldC + colOff + c] = v;
        }
    }
}

// ---------------- per-node attention logits: warp per (n,h) -------------------
template <int H, int C>
__global__ void alpha_k(const float* __restrict__ xl,
                        const float* __restrict__ a_src,
                        const float* __restrict__ a_dst) {
    int gw = (blockIdx.x * blockDim.x + threadIdx.x) >> 5;
    int lane = threadIdx.x & 31;
    if (gw >= N_NODES * H) return;
    int n = gw / H, h = gw - n * H;
    const float* row = xl + (size_t)n * (H * C) + h * C;
    float s1 = 0.f, s2 = 0.f;
#pragma unroll
    for (int c = lane; c < C; c += 32) {
        float v = row[c];
        s1 += v * a_src[h * C + c];
        s2 += v * a_dst[h * C + c];
    }
#pragma unroll
    for (int o = 16; o; o >>= 1) {
        s1 += __shfl_down_sync(0xffffffffu, s1, o);
        s2 += __shfl_down_sync(0xffffffffu, s2, o);
    }
    if (lane == 0) { g_als[gw] = s1; g_ald[gw] = s2; }
}

__device__ __forceinline__ float lrelu(float v) { return v > 0.f ? v : 0.2f * v; }

// ---------------- fused per-dst softmax + gather-aggregate (warp per dst) -----
// out[d, colOff + :HC] = relu( sum_e coef_e * xl[src_e] + bias )
template <int H, int C>
__global__ void gat_agg_k(const float* __restrict__ xl,
                          const float* __restrict__ bias,
                          float* __restrict__ out, int ldo, int colOff) {
    const int HC = H * C;
    const int CH4 = HC / 128;              // float4 chunks per lane
    __shared__ float sm_m[8][H];
    __shared__ float sm_r[8][H];
    int wid = threadIdx.x >> 5, lane = threadIdx.x & 31;
    int d = blockIdx.x * 8 + wid;
    if (d >= N_NODES) return;
    int beg = g_rs[d], end = g_rs[d + 1];

    // cache dst-side logit terms (static indexing only)
    float aldv[H];
#pragma unroll
    for (int h = 0; h < H; h++) aldv[h] = g_ald[d * H + h];

    // ---- pass A: per-head online max+sum over incident edges ----
    float m[H], s[H];
#pragma unroll
    for (int h = 0; h < H; h++) { m[h] = -1e30f; s[h] = 0.f; }
    for (int j = beg + lane; j < end; j += 32) {
        int src = g_csr[j];
#pragma unroll
        for (int h = 0; h < H; h++) {
            float v = lrelu(g_als[src * H + h] + aldv[h]);
            if (v > m[h]) { s[h] = s[h] * __expf(m[h] - v) + 1.f; m[h] = v; }
            else          { s[h] += __expf(v - m[h]); }
        }
    }
#pragma unroll
    for (int h = 0; h < H; h++) {
#pragma unroll
        for (int o = 16; o; o >>= 1) {
            float mo = __shfl_xor_sync(0xffffffffu, m[h], o);
            float so = __shfl_xor_sync(0xffffffffu, s[h], o);
            float M = fmaxf(m[h], mo);
            // -1e30 sentinel keeps everything finite (exp underflows to 0)
            s[h] = s[h] * __expf(m[h] - M) + so * __expf(mo - M);
            m[h] = M;
        }
    }
    if (lane == 0) {
#pragma unroll
        for (int h = 0; h < H; h++) { sm_m[wid][h] = m[h]; sm_r[wid][h] = 1.f / s[h]; }
    }
    __syncwarp();

    // ---- pass B: gather + weighted accumulate (float4 lanes) ----
    float4 acc[CH4];
#pragma unroll
    for (int k = 0; k < CH4; k++) acc[k] = make_float4(0.f, 0.f, 0.f, 0.f);
    for (int j = beg; j < end; j++) {
        int src = g_csr[j];
        const float4* xr = (const float4*)(xl + (size_t)src * HC);
#pragma unroll
        for (int k = 0; k < CH4; k++) {
            int h = (k * 128 + lane * 4) / C;    // head for this float4 (C%4==0)
            float v = lrelu(g_als[src * H + h] + g_ald[d * H + h]);
            float coef = __expf(v - sm_m[wid][h]) * sm_r[wid][h];
            float4 xv = xr[k * 32 + lane];
            acc[k].x += coef * xv.x; acc[k].y += coef * xv.y;
            acc[k].z += coef * xv.z; acc[k].w += coef * xv.w;
        }
    }

    // ---- epilogue: bias + relu, direct store (possibly into concat buffer) ----
    float4* orow = (float4*)(out + (size_t)d * ldo + colOff);
    const float4* b4 = (const float4*)bias;
#pragma unroll
    for (int k = 0; k < CH4; k++) {
        float4 bb = b4[k * 32 + lane];
        float4 r;
        r.x = fmaxf(acc[k].x + bb.x, 0.f);
        r.y = fmaxf(acc[k].y + bb.y, 0.f);
        r.z = fmaxf(acc[k].z + bb.z, 0.f);
        r.w = fmaxf(acc[k].w + bb.w, 0.f);
        orow[k * 32 + lane] = r;
    }
}

// ---------------- final: sigmoid(dot(xf2[n,:64], w) + b) ----------------------
__global__ void final_k(const float* __restrict__ xf2, const float* __restrict__ w,
                        const float* __restrict__ b, float* __restrict__ out) {
    int gw = (blockIdx.x * blockDim.x + threadIdx.x) >> 5;
    int lane = threadIdx.x & 31;
    if (gw >= N_NODES) return;
    const float* r = xf2 + (size_t)gw * 64;
    float s = r[lane] * w[lane] + r[lane + 32] * w[lane + 32];
#pragma unroll
    for (int o = 16; o; o >>= 1) s += __shfl_down_sync(0xffffffffu, s, o);
    if (lane == 0) out[gw] = 1.f / (1.f + expf(-(s + b[0])));
}

// =============================================================================
static inline dim3 gemm_grid(int K) { return dim3((K + 63) / 64, (N_NODES + 63) / 64); }
static inline int cdiv(int a, int b) { return (a + b - 1) / b; }

extern "C" void kernel_launch(void* const* d_in, const int* in_sizes, int n_in,
                              void* d_out, int out_size) {
    const float* x  = (const float*)d_in[0];
    const void*  ei = d_in[1];
    const float *W1 = (const float*)d_in[2],  *as1 = (const float*)d_in[3],
                *ad1 = (const float*)d_in[4], *b1  = (const float*)d_in[5];
    const float *W2 = (const float*)d_in[6],  *as2 = (const float*)d_in[7],
                *ad2 = (const float*)d_in[8], *b2  = (const float*)d_in[9];
    const float *W3 = (const float*)d_in[10], *as3 = (const float*)d_in[11],
                *ad3 = (const float*)d_in[12], *b3 = (const float*)d_in[13];
    const float *ln1_w = (const float*)d_in[14], *ln1_b = (const float*)d_in[15];
    const float *ln2_w = (const float*)d_in[16], *ln2_b = (const float*)d_in[17];
    const float *la1_w = (const float*)d_in[18], *la1_b = (const float*)d_in[19];
    const float *la3_w = (const float*)d_in[20], *la3_b = (const float*)d_in[21];
    const float *lf1_w = (const float*)d_in[22], *lf1_b = (const float*)d_in[23];
    const float *lf2_w = (const float*)d_in[24], *lf2_b = (const float*)d_in[25];
    const float *lf3_w = (const float*)d_in[26], *lf3_b = (const float*)d_in[27];
    float* out = (float*)d_out;

    float *xl, *x1, *x2, *t32, *xf0, *xf1, *xf2;
    cudaGetSymbolAddress((void**)&xl,  g_xl);
    cudaGetSymbolAddress((void**)&x1,  g_x1);
    cudaGetSymbolAddress((void**)&x2,  g_x2);
    cudaGetSymbolAddress((void**)&t32, g_t32);
    cudaGetSymbolAddress((void**)&xf0, g_xf0);
    cudaGetSymbolAddress((void**)&xf1, g_xf1);
    cudaGetSymbolAddress((void**)&xf2, g_xf2);

    // edge prep + CSR build
    detect_dtype_k<<<1, 1>>>((const int*)ei);
    zero_deg_k<<<cdiv(N_NODES, TB), TB>>>();
    prep_edges_k<<<cdiv(ET, TB), TB>>>(ei);
    scan_k<<<1, 1024>>>();
    scatter_k<<<cdiv(ET, TB), TB>>>();

    // dense gg path -> xf0[:, 0:32]
    gemm_k<<<gemm_grid(32), TB>>>(x,   ln1_w, ln1_b, t32, N_NODES, 16, 32, 1, 32, 0);
    gemm_k<<<gemm_grid(32), TB>>>(t32, ln2_w, ln2_b, xf0, N_NODES, 32, 32, 1, 1080, 0);

    // ---- conv1: 16 -> 8x32 -> x1 ----
    gemm_k<<<gemm_grid(256), TB>>>(x, W1, nullptr, xl, N_NODES, 16, 256, 0, 256, 0);
    alpha_k<8, 32><<<cdiv(N_NODES * 8 * 32, TB), TB>>>(xl, as1, ad1);
    gat_agg_k<8, 32><<<cdiv(N_NODES, 8), TB>>>(xl, b1, x1, 256, 0);

    // ---- conv2: 256 -> 8x32 -> x2 ----
    gemm_k<<<gemm_grid(256), TB>>>(x1, W2, nullptr, xl, N_NODES, 256, 256, 0, 256, 0);
    alpha_k<8, 32><<<cdiv(N_NODES * 8 * 32, TB), TB>>>(xl, as2, ad2);
    gat_agg_k<8, 32><<<cdiv(N_NODES, 8), TB>>>(xl, b2, x2, 256, 0);

    // ---- conv3: 256 -> 12x64 -> xf0[:, 32:800] ----
    gemm_k<<<gemm_grid(768), TB>>>(x2, W3, nullptr, xl, N_NODES, 256, 768, 0, 768, 0);
    alpha_k<12, 64><<<cdiv(N_NODES * 12 * 32, TB), TB>>>(xl, as3, ad3);
    gat_agg_k<12, 64><<<cdiv(N_NODES, 8), TB>>>(xl, b3, xf0, 1080, 32);

    // side dense paths -> xf0[:, 800:880], xf0[:, 880:1080]
    gemm_k<<<gemm_grid(80),  TB>>>(x1, la1_w, la1_b, xf0, N_NODES, 256, 80, 1, 1080, 800);
    gemm_k<<<gemm_grid(200), TB>>>(x2, la3_w, la3_b, xf0, N_NODES, 256, 200, 1, 1080, 880);

    // MLP head
    gemm_k<<<gemm_grid(200), TB>>>(xf0, lf1_w, lf1_b, xf1, N_NODES, 1080, 200, 1, 200, 0);
    gemm_k<<<gemm_grid(64),  TB>>>(xf1, lf2_w, lf2_b, xf2, N_NODES, 200, 64, 1, 64, 0);
    final_k<<<cdiv(N_NODES * 32, TB), TB>>>(xf2, lf3_w, lf3_b, out);
}

// round 6
// speedup vs baseline: 1.7234x; 1.4854x over previous
#include <cuda_runtime.h>
#include <mma.h>
#include <math.h>

using namespace nvcuda;

#define N_NODES 50000
#define N_EDGES 400000
#define ET (N_EDGES + N_NODES)   // 450000 edges incl. self-loops
#define TB 256
#define SCAN_B 1024
#define SCAN_G ((N_NODES + SCAN_B - 1) / SCAN_B)   // 49

// ---------------- scratch (device globals; no allocs allowed) ----------------
__device__ float g_xl [(size_t)N_NODES * 768];
__device__ float g_x1 [(size_t)N_NODES * 256];
__device__ float g_x2 [(size_t)N_NODES * 256];
__device__ float g_t32[(size_t)N_NODES * 32];
__device__ float g_xf0[(size_t)N_NODES * 1080];  // [gg | conv3 | xa1 | xa2]
__device__ float g_xf1[(size_t)N_NODES * 200];
__device__ float g_xf2[(size_t)N_NODES * 64];
__device__ float g_als[(size_t)N_NODES * 12];
__device__ float g_ald[(size_t)N_NODES * 12];
__device__ int   g_src[ET];
__device__ int   g_dst[ET];
__device__ int   g_deg[N_NODES];
__device__ int   g_rs [N_NODES + 1];
__device__ int   g_cur[N_NODES];
__device__ int   g_csr[ET];
__device__ int   g_bsum[SCAN_G];
__device__ int   g_boff[SCAN_G];
__device__ int   g_is64;

// ---------------- dtype probe ------------------------------------------------
__global__ void detect_dtype_k(const int* __restrict__ ei32) {
    int all_zero = 1;
#pragma unroll
    for (int i = 0; i < 16; i++)
        if (ei32[2 * i + 1] != 0) all_zero = 0;
    g_is64 = all_zero;
}

__global__ void zero_deg_k() {
    int i = blockIdx.x * blockDim.x + threadIdx.x;
    if (i < N_NODES) g_deg[i] = 0;
}

// ---------------- edge prep: decode + self loops + degree histogram -----------
__global__ void prep_edges_k(const void* __restrict__ ei) {
    int i = blockIdx.x * blockDim.x + threadIdx.x;
    if (i >= ET) return;
    int s, d;
    if (i < N_EDGES) {
        if (g_is64) {
            const long long* p = (const long long*)ei;
            s = (int)p[i]; d = (int)p[N_EDGES + i];
        } else {
            const int* p = (const int*)ei;
            s = p[i]; d = p[N_EDGES + i];
        }
    } else {
        s = d = i - N_EDGES;
    }
    g_src[i] = s;
    g_dst[i] = d;
    atomicAdd(&g_deg[d], 1);
}

// ---------------- deterministic 3-phase scan ----------------------------------
__global__ void scan1_k() {
    __shared__ int sh[SCAN_B];
    int b = blockIdx.x, t = threadIdx.x;
    int idx = b * SCAN_B + t;
    int v = (idx < N_NODES) ? g_deg[idx] : 0;
    sh[t] = v;
    __syncthreads();
    for (int o = 1; o < SCAN_B; o <<= 1) {
        int u = (t >= o) ? sh[t - o] : 0;
        __syncthreads();
        sh[t] += u;
        __syncthreads();
    }
    if (idx < N_NODES) g_rs[idx] = sh[t] - v;   // exclusive within block
    if (t == SCAN_B - 1) g_bsum[b] = sh[t];
}

__global__ void scan2_k() {
    if (threadIdx.x == 0) {
        int run = 0;
        for (int b = 0; b < SCAN_G; b++) { g_boff[b] = run; run += g_bsum[b]; }
    }
}

__global__ void scan3_k() {
    int idx = blockIdx.x * SCAN_B + threadIdx.x;
    if (idx < N_NODES) {
        int v = g_rs[idx] + g_boff[blockIdx.x];
        g_rs[idx] = v;
        g_cur[idx] = v;
    }
    if (idx == 0) g_rs[N_NODES] = ET;
}

__global__ void scatter_k() {
    int e = blockIdx.x * blockDim.x + threadIdx.x;
    if (e >= ET) return;
    int pos = atomicAdd(&g_cur[g_dst[e]], 1);
    g_csr[pos] = g_src[e];
}

// ---------------- TF32 tensor-core GEMM ---------------------------------------
// C[:, colOff:colOff+K] = act(A[Nr,M] @ B[M,K] + bias); block tile 128x64, 8 warps
#define BM 128
#define BN 64
#define BK 16

__global__ void gemm_k(const float* __restrict__ A, const float* __restrict__ B,
                       const float* __restrict__ bias, float* __restrict__ C,
                       int Nr, int M, int K, int act, int ldC, int colOff) {
    __shared__ float As[BM][BK];        // 8 KB
    __shared__ float Bs[BK][BN + 8];    // 4.5 KB (pad keeps frag rows conflict-light)
    __shared__ float Cs[BM][BN + 4];    // 34 KB staging for epilogue
    int tid = threadIdx.x;
    int wid = tid >> 5;
    int wm = wid >> 1;         // 0..3 -> 32-row slab
    int wn = wid & 1;          // 0..1 -> 32-col slab
    int rowBase = blockIdx.y * BM;
    int colBase = blockIdx.x * BN;

    wmma::fragment<wmma::accumulator, 16, 16, 8, float> acc[2][2];
#pragma unroll
    for (int i = 0; i < 2; i++)
#pragma unroll
        for (int j = 0; j < 2; j++) wmma::fill_fragment(acc[i][j], 0.f);

    for (int k0 = 0; k0 < M; k0 += BK) {
        for (int i = tid; i < BM * BK; i += 256) {
            int r = i >> 4, k = i & 15;
            int gr = rowBase + r, gk = k0 + k;
            As[r][k] = (gr < Nr && gk < M) ? A[(size_t)gr * M + gk] : 0.f;
        }
        for (int i = tid; i < BK * BN; i += 256) {
            int k = i >> 6, n = i & 63;
            int gk = k0 + k, gc = colBase + n;
            Bs[k][n] = (gk < M && gc < K) ? B[(size_t)gk * K + gc] : 0.f;
        }
        __syncthreads();
#pragma unroll
        for (int ks = 0; ks < 2; ks++) {
            wmma::fragment<wmma::matrix_a, 16, 16, 8, wmma::precision::tf32, wmma::row_major> af[2];
            wmma::fragment<wmma::matrix_b, 16, 16, 8, wmma::precision::tf32, wmma::row_major> bf[2];
#pragma unroll
            for (int i = 0; i < 2; i++) {
                wmma::load_matrix_sync(af[i], &As[wm * 32 + i * 16][ks * 8], BK);
#pragma unroll
                for (int e = 0; e < af[i].num_elements; e++)
                    af[i].x[e] = wmma::__float_to_tf32(af[i].x[e]);
            }
#pragma unroll
            for (int j = 0; j < 2; j++) {
                wmma::load_matrix_sync(bf[j], &Bs[ks * 8][wn * 32 + j * 16], BN + 8);
#pragma unroll
                for (int e = 0; e < bf[j].num_elements; e++)
                    bf[j].x[e] = wmma::__float_to_tf32(bf[j].x[e]);
            }
#pragma unroll
            for (int i = 0; i < 2; i++)
#pragma unroll
                for (int j = 0; j < 2; j++)
                    wmma::mma_sync(acc[i][j], af[i], bf[j], acc[i][j]);
        }
        __syncthreads();
    }

    // stage to shared, then cooperative guarded write with bias+act
#pragma unroll
    for (int i = 0; i < 2; i++)
#pragma unroll
        for (int j = 0; j < 2; j++)
            wmma::store_matrix_sync(&Cs[wm * 32 + i * 16][wn * 32 + j * 16],
                                    acc[i][j], BN + 4, wmma::mem_row_major);
    __syncthreads();
    for (int i = tid; i < BM * BN; i += 256) {
        int r = i >> 6, c = i & 63;
        int gr = rowBase + r, gc = colBase + c;
        if (gr >= Nr || gc >= K) continue;
        float v = Cs[r][c] + (bias ? bias[gc] : 0.f);
        if (act) v = fmaxf(v, 0.f);
        C[(size_t)gr * ldC + colOff + gc] = v;
    }
}

// ---------------- per-node attention logits: warp per (n,h) -------------------
template <int H, int C>
__global__ void alpha_k(const float* __restrict__ xl,
                        const float* __restrict__ a_src,
                        const float* __restrict__ a_dst) {
    int gw = (blockIdx.x * blockDim.x + threadIdx.x) >> 5;
    int lane = threadIdx.x & 31;
    if (gw >= N_NODES * H) return;
    int n = gw / H, h = gw - n * H;
    const float* row = xl + (size_t)n * (H * C) + h * C;
    float s1 = 0.f, s2 = 0.f;
#pragma unroll
    for (int c = lane; c < C; c += 32) {
        float v = row[c];
        s1 += v * a_src[h * C + c];
        s2 += v * a_dst[h * C + c];
    }
#pragma unroll
    for (int o = 16; o; o >>= 1) {
        s1 += __shfl_down_sync(0xffffffffu, s1, o);
        s2 += __shfl_down_sync(0xffffffffu, s2, o);
    }
    if (lane == 0) { g_als[gw] = s1; g_ald[gw] = s2; }
}

__device__ __forceinline__ float lrelu(float v) { return v > 0.f ? v : 0.2f * v; }

// ---------------- fused per-dst softmax + gather-aggregate (warp per dst) -----
template <int H, int C>
__global__ void gat_agg_k(const float* __restrict__ xl,
                          const float* __restrict__ bias,
                          float* __restrict__ out, int ldo, int colOff) {
    const int HC = H * C;
    const int CH4 = HC / 128;              // float4 chunks per lane
    __shared__ float sm_m[8][H];
    __shared__ float sm_r[8][H];
    int wid = threadIdx.x >> 5, lane = threadIdx.x & 31;
    int d = blockIdx.x * 8 + wid;
    if (d >= N_NODES) return;
    int beg = g_rs[d], end = g_rs[d + 1];

    float aldv[H];
#pragma unroll
    for (int h = 0; h < H; h++) aldv[h] = g_ald[d * H + h];

    // ---- pass A: per-head online max+sum over incident edges ----
    float m[H], s[H];
#pragma unroll
    for (int h = 0; h < H; h++) { m[h] = -1e30f; s[h] = 0.f; }
    for (int j = beg + lane; j < end; j += 32) {
        int src = g_csr[j];
#pragma unroll
        for (int h = 0; h < H; h++) {
            float v = lrelu(g_als[src * H + h] + aldv[h]);
            if (v > m[h]) { s[h] = s[h] * __expf(m[h] - v) + 1.f; m[h] = v; }
            else          { s[h] += __expf(v - m[h]); }
        }
    }
#pragma unroll
    for (int h = 0; h < H; h++) {
#pragma unroll
        for (int o = 16; o; o >>= 1) {
            float mo = __shfl_xor_sync(0xffffffffu, m[h], o);
            float so = __shfl_xor_sync(0xffffffffu, s[h], o);
            float M = fmaxf(m[h], mo);
            s[h] = s[h] * __expf(m[h] - M) + so * __expf(mo - M);
            m[h] = M;
        }
    }
    if (lane == 0) {
#pragma unroll
        for (int h = 0; h < H; h++) { sm_m[wid][h] = m[h]; sm_r[wid][h] = 1.f / s[h]; }
    }
    __syncwarp();

    // per-lane head constants for coef broadcast (lane h owns head h)
    float ald_l = 0.f, m_l = 0.f, r_l = 0.f;
    if (lane < H) {
        ald_l = aldv[0];   // overwritten below via shared to avoid dynamic reg index
        m_l = sm_m[wid][lane];
        r_l = sm_r[wid][lane];
        ald_l = g_ald[d * H + lane];
    }
    // per-lane chunk->head map (compile-time unrolled)
    int hmap[CH4];
#pragma unroll
    for (int k = 0; k < CH4; k++) hmap[k] = (k * 128 + lane * 4) / C;

    // ---- pass B: gather + weighted accumulate; coef via lane-exp + shfl ----
    float4 acc[CH4];
#pragma unroll
    for (int k = 0; k < CH4; k++) acc[k] = make_float4(0.f, 0.f, 0.f, 0.f);
    for (int j = beg; j < end; j++) {
        int src = g_csr[j];
        float cl = 0.f;
        if (lane < H)
            cl = __expf(lrelu(g_als[src * H + lane] + ald_l) - m_l) * r_l;
        const float4* xr = (const float4*)(xl + (size_t)src * HC);
#pragma unroll
        for (int k = 0; k < CH4; k++) {
            float coef = __shfl_sync(0xffffffffu, cl, hmap[k]);
            float4 xv = xr[k * 32 + lane];
            acc[k].x += coef * xv.x; acc[k].y += coef * xv.y;
            acc[k].z += coef * xv.z; acc[k].w += coef * xv.w;
        }
    }

    // ---- epilogue: bias + relu, direct store ----
    float4* orow = (float4*)(out + (size_t)d * ldo + colOff);
    const float4* b4 = (const float4*)bias;
#pragma unroll
    for (int k = 0; k < CH4; k++) {
        float4 bb = b4[k * 32 + lane];
        float4 r;
        r.x = fmaxf(acc[k].x + bb.x, 0.f);
        r.y = fmaxf(acc[k].y + bb.y, 0.f);
        r.z = fmaxf(acc[k].z + bb.z, 0.f);
        r.w = fmaxf(acc[k].w + bb.w, 0.f);
        orow[k * 32 + lane] = r;
    }
}

// ---------------- final: sigmoid(dot(xf2[n,:64], w) + b) ----------------------
__global__ void final_k(const float* __restrict__ xf2, const float* __restrict__ w,
                        const float* __restrict__ b, float* __restrict__ out) {
    int gw = (blockIdx.x * blockDim.x + threadIdx.x) >> 5;
    int lane = threadIdx.x & 31;
    if (gw >= N_NODES) return;
    const float* r = xf2 + (size_t)gw * 64;
    float s = r[lane] * w[lane] + r[lane + 32] * w[lane + 32];
#pragma unroll
    for (int o = 16; o; o >>= 1) s += __shfl_down_sync(0xffffffffu, s, o);
    if (lane == 0) out[gw] = 1.f / (1.f + expf(-(s + b[0])));
}

// =============================================================================
static inline dim3 gemm_grid(int K) { return dim3((K + BN - 1) / BN, (N_NODES + BM - 1) / BM); }
static inline int cdiv(int a, int b) { return (a + b - 1) / b; }

extern "C" void kernel_launch(void* const* d_in, const int* in_sizes, int n_in,
                              void* d_out, int out_size) {
    const float* x  = (const float*)d_in[0];
    const void*  ei = d_in[1];
    const float *W1 = (const float*)d_in[2],  *as1 = (const float*)d_in[3],
                *ad1 = (const float*)d_in[4], *b1  = (const float*)d_in[5];
    const float *W2 = (const float*)d_in[6],  *as2 = (const float*)d_in[7],
                *ad2 = (const float*)d_in[8], *b2  = (const float*)d_in[9];
    const float *W3 = (const float*)d_in[10], *as3 = (const float*)d_in[11],
                *ad3 = (const float*)d_in[12], *b3 = (const float*)d_in[13];
    const float *ln1_w = (const float*)d_in[14], *ln1_b = (const float*)d_in[15];
    const float *ln2_w = (const float*)d_in[16], *ln2_b = (const float*)d_in[17];
    const float *la1_w = (const float*)d_in[18], *la1_b = (const float*)d_in[19];
    const float *la3_w = (const float*)d_in[20], *la3_b = (const float*)d_in[21];
    const float *lf1_w = (const float*)d_in[22], *lf1_b = (const float*)d_in[23];
    const float *lf2_w = (const float*)d_in[24], *lf2_b = (const float*)d_in[25];
    const float *lf3_w = (const float*)d_in[26], *lf3_b = (const float*)d_in[27];
    float* out = (float*)d_out;

    float *xl, *x1, *x2, *t32, *xf0, *xf1, *xf2;
    cudaGetSymbolAddress((void**)&xl,  g_xl);
    cudaGetSymbolAddress((void**)&x1,  g_x1);
    cudaGetSymbolAddress((void**)&x2,  g_x2);
    cudaGetSymbolAddress((void**)&t32, g_t32);
    cudaGetSymbolAddress((void**)&xf0, g_xf0);
    cudaGetSymbolAddress((void**)&xf1, g_xf1);
    cudaGetSymbolAddress((void**)&xf2, g_xf2);

    // edge prep + CSR build
    detect_dtype_k<<<1, 1>>>((const int*)ei);
    zero_deg_k<<<cdiv(N_NODES, TB), TB>>>();
    prep_edges_k<<<cdiv(ET, TB), TB>>>(ei);
    scan1_k<<<SCAN_G, SCAN_B>>>();
    scan2_k<<<1, 32>>>();
    scan3_k<<<SCAN_G, SCAN_B>>>();
    scatter_k<<<cdiv(ET, TB), TB>>>();

    // dense gg path -> xf0[:, 0:32]
    gemm_k<<<gemm_grid(32), TB>>>(x,   ln1_w, ln1_b, t32, N_NODES, 16, 32, 1, 32, 0);
    gemm_k<<<gemm_grid(32), TB>>>(t32, ln2_w, ln2_b, xf0, N_NODES, 32, 32, 1, 1080, 0);

    // ---- conv1: 16 -> 8x32 -> x1 ----
    gemm_k<<<gemm_grid(256), TB>>>(x, W1, nullptr, xl, N_NODES, 16, 256, 0, 256, 0);
    alpha_k<8, 32><<<cdiv(N_NODES * 8 * 32, TB), TB>>>(xl, as1, ad1);
    gat_agg_k<8, 32><<<cdiv(N_NODES, 8), TB>>>(xl, b1, x1, 256, 0);

    // ---- conv2: 256 -> 8x32 -> x2 ----
    gemm_k<<<gemm_grid(256), TB>>>(x1, W2, nullptr, xl, N_NODES, 256, 256, 0, 256, 0);
    alpha_k<8, 32><<<cdiv(N_NODES * 8 * 32, TB), TB>>>(xl, as2, ad2);
    gat_agg_k<8, 32><<<cdiv(N_NODES, 8), TB>>>(xl, b2, x2, 256, 0);

    // ---- conv3: 256 -> 12x64 -> xf0[:, 32:800] ----
    gemm_k<<<gemm_grid(768), TB>>>(x2, W3, nullptr, xl, N_NODES, 256, 768, 0, 768, 0);
    alpha_k<12, 64><<<cdiv(N_NODES * 12 * 32, TB), TB>>>(xl, as3, ad3);
    gat_agg_k<12, 64><<<cdiv(N_NODES, 8), TB>>>(xl, b3, xf0, 1080, 32);

    // side dense paths -> xf0[:, 800:880], xf0[:, 880:1080]
    gemm_k<<<gemm_grid(80),  TB>>>(x1, la1_w, la1_b, xf0, N_NODES, 256, 80, 1, 1080, 800);
    gemm_k<<<gemm_grid(200), TB>>>(x2, la3_w, la3_b, xf0, N_NODES, 256, 200, 1, 1080, 880);

    // MLP head
    gemm_k<<<gemm_grid(200), TB>>>(xf0, lf1_w, lf1_b, xf1, N_NODES, 1080, 200, 1, 200, 0);
    gemm_k<<<gemm_grid(64),  TB>>>(xf1, lf2_w, lf2_b, xf2, N_NODES, 200, 64, 1, 64, 0);
    final_k<<<cdiv(N_NODES * 32, TB), TB>>>(xf2, lf3_w, lf3_b, out);
}

// round 7
// speedup vs baseline: 2.3435x; 1.3598x over previous
#include <cuda_runtime.h>
#include <mma.h>
#include <math.h>

using namespace nvcuda;

#define N_NODES 50000
#define N_EDGES 400000
#define ET (N_EDGES + N_NODES)   // 450000 edges incl. self-loops
#define TB 256
#define SCAN_B 1024
#define SCAN_G ((N_NODES + SCAN_B - 1) / SCAN_B)   // 49

// ---------------- scratch (device globals; no allocs allowed) ----------------
__device__ float g_xl [(size_t)N_NODES * 768];
__device__ float g_x1 [(size_t)N_NODES * 256];
__device__ float g_x2 [(size_t)N_NODES * 256];
__device__ float g_t32[(size_t)N_NODES * 32];
__device__ float g_xf0[(size_t)N_NODES * 1080];  // [gg | conv3 | xa1 | xa2]
__device__ float g_xf1[(size_t)N_NODES * 200];
__device__ float g_xf2[(size_t)N_NODES * 64];
__device__ float g_als[(size_t)N_NODES * 12];
__device__ float g_ald[(size_t)N_NODES * 12];
__device__ float g_m  [(size_t)N_NODES * 12];    // per-dst softmax max
__device__ float g_den[(size_t)N_NODES * 12];    // per-dst 1/sum
__device__ float g_ex [(size_t)ET * 12];         // CSR-ordered coefficients
__device__ int   g_src[ET];
__device__ int   g_dst[ET];
__device__ int   g_pos[ET];                      // edge -> CSR slot
__device__ int   g_deg[N_NODES];
__device__ int   g_rs [N_NODES + 1];
__device__ int   g_cur[N_NODES];
__device__ int   g_csr[ET];                      // CSR slot -> src node
__device__ int   g_bsum[SCAN_G];
__device__ int   g_boff[SCAN_G];
__device__ int   g_is64;

// ---------------- dtype probe ------------------------------------------------
__global__ void detect_dtype_k(const int* __restrict__ ei32) {
    int all_zero = 1;
#pragma unroll
    for (int i = 0; i < 16; i++)
        if (ei32[2 * i + 1] != 0) all_zero = 0;
    g_is64 = all_zero;
}

__global__ void zero_deg_k() {
    int i = blockIdx.x * blockDim.x + threadIdx.x;
    if (i < N_NODES) g_deg[i] = 0;
}

__global__ void prep_edges_k(const void* __restrict__ ei) {
    int i = blockIdx.x * blockDim.x + threadIdx.x;
    if (i >= ET) return;
    int s, d;
    if (i < N_EDGES) {
        if (g_is64) {
            const long long* p = (const long long*)ei;
            s = (int)p[i]; d = (int)p[N_EDGES + i];
        } else {
            const int* p = (const int*)ei;
            s = p[i]; d = p[N_EDGES + i];
        }
    } else {
        s = d = i - N_EDGES;
    }
    g_src[i] = s;
    g_dst[i] = d;
    atomicAdd(&g_deg[d], 1);
}

// ---------------- deterministic 3-phase scan ----------------------------------
__global__ void scan1_k() {
    __shared__ int sh[SCAN_B];
    int b = blockIdx.x, t = threadIdx.x;
    int idx = b * SCAN_B + t;
    int v = (idx < N_NODES) ? g_deg[idx] : 0;
    sh[t] = v;
    __syncthreads();
    for (int o = 1; o < SCAN_B; o <<= 1) {
        int u = (t >= o) ? sh[t - o] : 0;
        __syncthreads();
        sh[t] += u;
        __syncthreads();
    }
    if (idx < N_NODES) g_rs[idx] = sh[t] - v;
    if (t == SCAN_B - 1) g_bsum[b] = sh[t];
}

__global__ void scan2_k() {
    if (threadIdx.x == 0) {
        int run = 0;
        for (int b = 0; b < SCAN_G; b++) { g_boff[b] = run; run += g_bsum[b]; }
    }
}

__global__ void scan3_k() {
    int idx = blockIdx.x * SCAN_B + threadIdx.x;
    if (idx < N_NODES) {
        int v = g_rs[idx] + g_boff[blockIdx.x];
        g_rs[idx] = v;
        g_cur[idx] = v;
    }
    if (idx == 0) g_rs[N_NODES] = ET;
}

__global__ void scatter_k() {
    int e = blockIdx.x * blockDim.x + threadIdx.x;
    if (e >= ET) return;
    int pos = atomicAdd(&g_cur[g_dst[e]], 1);
    g_csr[pos] = g_src[e];
    g_pos[e] = pos;
}

// ---------------- TF32 tensor-core GEMM, cp.async double-buffered -------------
#define BM 128
#define BN 64
#define BK 16

__device__ __forceinline__ void cpa16(float* dst, const float* src, bool valid) {
    unsigned d = (unsigned)__cvta_generic_to_shared(dst);
    int sz = valid ? 16 : 0;
    asm volatile("cp.async.ca.shared.global [%0], [%1], 16, %2;\n"
                 :: "r"(d), "l"(src), "r"(sz));
}

// smem union: stage buffers alias the epilogue staging tile
//  A stages: 2*128*16 fl = 16 KB @0      B stages: 2*16*72 fl = 9 KB @16K
//  Cs (epilogue): 128*68 fl = 34.8 KB @0
__global__ void gemm_k(const float* __restrict__ A, const float* __restrict__ B,
                       const float* __restrict__ bias, float* __restrict__ C,
                       int Nr, int M, int K, int act, int ldC, int colOff) {
    __shared__ __align__(16) unsigned char smem_raw[34816];
    float* As = (float*)smem_raw;                         // [2][128][16]
    float* Bs = (float*)(smem_raw + 16384);               // [2][16][72]
    float* Cs = (float*)smem_raw;                         // [128][68]
    int tid = threadIdx.x;
    int wid = tid >> 5;
    int wm = wid >> 1;
    int wn = wid & 1;
    int rowBase = blockIdx.y * BM;
    int colBase = blockIdx.x * BN;

    wmma::fragment<wmma::accumulator, 16, 16, 8, float> acc[2][2];
#pragma unroll
    for (int i = 0; i < 2; i++)
#pragma unroll
        for (int j = 0; j < 2; j++) wmma::fill_fragment(acc[i][j], 0.f);

    int nt = (M + BK - 1) / BK;

    auto load_tile = [&](int k0, int buf) {
        // A: 512 float4 (128 rows x 4 float4)
        for (int i = tid; i < 512; i += 256) {
            int r = i >> 2, c4 = i & 3;
            int gr = rowBase + r, gk = k0 + c4 * 4;
            bool v = (gr < Nr) && (gk + 4 <= M);
            const float* src = v ? (A + (size_t)gr * M + gk) : A;
            cpa16(As + buf * 2048 + r * 16 + c4 * 4, src, v);
        }
        // B: 256 float4 (16 rows x 16 float4)
        {
            int r = tid >> 4, c4 = tid & 15;
            int gk = k0 + r, gc = colBase + c4 * 4;
            bool v = (gk < M) && (gc + 4 <= K);
            const float* src = v ? (B + (size_t)gk * K + gc) : B;
            cpa16(Bs + buf * 1152 + r * 72 + c4 * 4, src, v);
        }
        asm volatile("cp.async.commit_group;\n");
    };

    load_tile(0, 0);
    for (int t = 0; t < nt; t++) {
        if (t + 1 < nt) {
            load_tile((t + 1) * BK, (t + 1) & 1);
            asm volatile("cp.async.wait_group 1;\n");
        } else {
            asm volatile("cp.async.wait_group 0;\n");
        }
        __syncthreads();
        int buf = t & 1;
        float* Ab = As + buf * 2048;
        float* Bb = Bs + buf * 1152;
#pragma unroll
        for (int ks = 0; ks < 2; ks++) {
            wmma::fragment<wmma::matrix_a, 16, 16, 8, wmma::precision::tf32, wmma::row_major> af[2];
            wmma::fragment<wmma::matrix_b, 16, 16, 8, wmma::precision::tf32, wmma::row_major> bf[2];
#pragma unroll
            for (int i = 0; i < 2; i++) {
                wmma::load_matrix_sync(af[i], Ab + (wm * 32 + i * 16) * 16 + ks * 8, BK);
#pragma unroll
                for (int e = 0; e < af[i].num_elements; e++)
                    af[i].x[e] = wmma::__float_to_tf32(af[i].x[e]);
            }
#pragma unroll
            for (int j = 0; j < 2; j++) {
                wmma::load_matrix_sync(bf[j], Bb + (ks * 8) * 72 + wn * 32 + j * 16, 72);
#pragma unroll
                for (int e = 0; e < bf[j].num_elements; e++)
                    bf[j].x[e] = wmma::__float_to_tf32(bf[j].x[e]);
            }
#pragma unroll
            for (int i = 0; i < 2; i++)
#pragma unroll
                for (int j = 0; j < 2; j++)
                    wmma::mma_sync(acc[i][j], af[i], bf[j], acc[i][j]);
        }
        __syncthreads();
    }

    // epilogue: stage accumulators into (aliased) Cs, then guarded global write
#pragma unroll
    for (int i = 0; i < 2; i++)
#pragma unroll
        for (int j = 0; j < 2; j++)
            wmma::store_matrix_sync(Cs + (wm * 32 + i * 16) * 68 + wn * 32 + j * 16,
                                    acc[i][j], 68, wmma::mem_row_major);
    __syncthreads();
    for (int i = tid; i < BM * BN; i += 256) {
        int r = i >> 6, c = i & 63;
        int gr = rowBase + r, gc = colBase + c;
        if (gr >= Nr || gc >= K) continue;
        float v = Cs[r * 68 + c] + (bias ? bias[gc] : 0.f);
        if (act) v = fmaxf(v, 0.f);
        C[(size_t)gr * ldC + colOff + gc] = v;
    }
}

// ---------------- per-node attention logits: warp per (n,h) -------------------
template <int H, int C>
__global__ void alpha_k(const float* __restrict__ xl,
                        const float* __restrict__ a_src,
                        const float* __restrict__ a_dst) {
    int gw = (blockIdx.x * blockDim.x + threadIdx.x) >> 5;
    int lane = threadIdx.x & 31;
    if (gw >= N_NODES * H) return;
    int n = gw / H, h = gw - n * H;
    const float* row = xl + (size_t)n * (H * C) + h * C;
    float s1 = 0.f, s2 = 0.f;
#pragma unroll
    for (int c = lane; c < C; c += 32) {
        float v = row[c];
        s1 += v * a_src[h * C + c];
        s2 += v * a_dst[h * C + c];
    }
#pragma unroll
    for (int o = 16; o; o >>= 1) {
        s1 += __shfl_down_sync(0xffffffffu, s1, o);
        s2 += __shfl_down_sync(0xffffffffu, s2, o);
    }
    if (lane == 0) { g_als[gw] = s1; g_ald[gw] = s2; }
}

__device__ __forceinline__ float lrelu(float v) { return v > 0.f ? v : 0.2f * v; }

// ---------------- stats: per-dst online softmax (m, 1/den) --------------------
template <int H>
__global__ void stats_k() {
    int wid = threadIdx.x >> 5, lane = threadIdx.x & 31;
    int d = blockIdx.x * 8 + wid;
    if (d >= N_NODES) return;
    int beg = g_rs[d], end = g_rs[d + 1];
    float aldv[H];
#pragma unroll
    for (int h = 0; h < H; h++) aldv[h] = g_ald[d * H + h];
    float m[H], s[H];
#pragma unroll
    for (int h = 0; h < H; h++) { m[h] = -1e30f; s[h] = 0.f; }
    for (int j = beg + lane; j < end; j += 32) {
        int src = g_csr[j];
#pragma unroll
        for (int h = 0; h < H; h++) {
            float v = lrelu(g_als[src * H + h] + aldv[h]);
            if (v > m[h]) { s[h] = s[h] * __expf(m[h] - v) + 1.f; m[h] = v; }
            else          { s[h] += __expf(v - m[h]); }
        }
    }
#pragma unroll
    for (int h = 0; h < H; h++) {
#pragma unroll
        for (int o = 16; o; o >>= 1) {
            float mo = __shfl_xor_sync(0xffffffffu, m[h], o);
            float so = __shfl_xor_sync(0xffffffffu, s[h], o);
            float M = fmaxf(m[h], mo);
            s[h] = s[h] * __expf(m[h] - M) + so * __expf(mo - M);
            m[h] = M;
        }
    }
    if (lane == 0) {
#pragma unroll
        for (int h = 0; h < H; h++) {
            g_m[d * H + h] = m[h];
            g_den[d * H + h] = 1.f / s[h];
        }
    }
}

// ---------------- coef: edge-parallel coefficient materialization -------------
template <int H>
__global__ void coef_k() {
    int i = blockIdx.x * blockDim.x + threadIdx.x;
    if (i >= ET * H) return;
    int e = i / H, h = i - e * H;
    int s = g_src[e], d = g_dst[e];
    float v = lrelu(g_als[s * H + h] + g_ald[d * H + h]);
    float coef = __expf(v - g_m[d * H + h]) * g_den[d * H + h];
    g_ex[(size_t)g_pos[e] * H + h] = coef;
}

// ---------------- agg: warp per (dst, 128-float chunk) ------------------------
template <int H, int C>
__global__ void agg_k(const float* __restrict__ xl, const float* __restrict__ bias,
                      float* __restrict__ out, int ldo, int colOff) {
    const int HC = H * C;
    const int CH = HC / 128;
    int w = (blockIdx.x * blockDim.x + threadIdx.x) >> 5;
    int lane = threadIdx.x & 31;
    if (w >= N_NODES * CH) return;
    int d = w / CH, c = w - d * CH;
    int beg = g_rs[d], end = g_rs[d + 1];
    int col = c * 128 + lane * 4;
    int hm = col / C;
    const float4* xbase = (const float4*)xl + (col >> 2);
    float4 acc = make_float4(0.f, 0.f, 0.f, 0.f);
    for (int j = beg; j < end; j++) {
        int src = g_csr[j];
        float coef = g_ex[(size_t)j * H + hm];
        float4 xv = xbase[(size_t)src * (HC / 4)];
        acc.x += coef * xv.x; acc.y += coef * xv.y;
        acc.z += coef * xv.z; acc.w += coef * xv.w;
    }
    float4 bb = *(const float4*)(bias + col);
    float4 r;
    r.x = fmaxf(acc.x + bb.x, 0.f);
    r.y = fmaxf(acc.y + bb.y, 0.f);
    r.z = fmaxf(acc.z + bb.z, 0.f);
    r.w = fmaxf(acc.w + bb.w, 0.f);
    *(float4*)(out + (size_t)d * ldo + colOff + col) = r;
}

// ---------------- final: sigmoid(dot(xf2[n,:64], w) + b) ----------------------
__global__ void final_k(const float* __restrict__ xf2, const float* __restrict__ w,
                        const float* __restrict__ b, float* __restrict__ out) {
    int gw = (blockIdx.x * blockDim.x + threadIdx.x) >> 5;
    int lane = threadIdx.x & 31;
    if (gw >= N_NODES) return;
    const float* r = xf2 + (size_t)gw * 64;
    float s = r[lane] * w[lane] + r[lane + 32] * w[lane + 32];
#pragma unroll
    for (int o = 16; o; o >>= 1) s += __shfl_down_sync(0xffffffffu, s, o);
    if (lane == 0) out[gw] = 1.f / (1.f + expf(-(s + b[0])));
}

// =============================================================================
static inline dim3 gemm_grid(int K) { return dim3((K + BN - 1) / BN, (N_NODES + BM - 1) / BM); }
static inline int cdiv(int a, int b) { return (a + b - 1) / b; }

extern "C" void kernel_launch(void* const* d_in, const int* in_sizes, int n_in,
                              void* d_out, int out_size) {
    const float* x  = (const float*)d_in[0];
    const void*  ei = d_in[1];
    const float *W1 = (const float*)d_in[2],  *as1 = (const float*)d_in[3],
                *ad1 = (const float*)d_in[4], *b1  = (const float*)d_in[5];
    const float *W2 = (const float*)d_in[6],  *as2 = (const float*)d_in[7],
                *ad2 = (const float*)d_in[8], *b2  = (const float*)d_in[9];
    const float *W3 = (const float*)d_in[10], *as3 = (const float*)d_in[11],
                *ad3 = (const float*)d_in[12], *b3 = (const float*)d_in[13];
    const float *ln1_w = (const float*)d_in[14], *ln1_b = (const float*)d_in[15];
    const float *ln2_w = (const float*)d_in[16], *ln2_b = (const float*)d_in[17];
    const float *la1_w = (const float*)d_in[18], *la1_b = (const float*)d_in[19];
    const float *la3_w = (const float*)d_in[20], *la3_b = (const float*)d_in[21];
    const float *lf1_w = (const float*)d_in[22], *lf1_b = (const float*)d_in[23];
    const float *lf2_w = (const float*)d_in[24], *lf2_b = (const float*)d_in[25];
    const float *lf3_w = (const float*)d_in[26], *lf3_b = (const float*)d_in[27];
    float* out = (float*)d_out;

    float *xl, *x1, *x2, *t32, *xf0, *xf1, *xf2;
    cudaGetSymbolAddress((void**)&xl,  g_xl);
    cudaGetSymbolAddress((void**)&x1,  g_x1);
    cudaGetSymbolAddress((void**)&x2,  g_x2);
    cudaGetSymbolAddress((void**)&t32, g_t32);
    cudaGetSymbolAddress((void**)&xf0, g_xf0);
    cudaGetSymbolAddress((void**)&xf1, g_xf1);
    cudaGetSymbolAddress((void**)&xf2, g_xf2);

    // edge prep (conv1 GEMM interleaved early for profiler visibility)
    detect_dtype_k<<<1, 1>>>((const int*)ei);
    zero_deg_k<<<cdiv(N_NODES, TB), TB>>>();
    prep_edges_k<<<cdiv(ET, TB), TB>>>(ei);
    gemm_k<<<gemm_grid(256), TB>>>(x, W1, nullptr, xl, N_NODES, 16, 256, 0, 256, 0);
    scan1_k<<<SCAN_G, SCAN_B>>>();
    scan2_k<<<1, 32>>>();
    scan3_k<<<SCAN_G, SCAN_B>>>();
    scatter_k<<<cdiv(ET, TB), TB>>>();

    // ---- conv1: 16 -> 8x32 -> x1 ----
    alpha_k<8, 32><<<cdiv(N_NODES * 8 * 32, TB), TB>>>(xl, as1, ad1);
    stats_k<8><<<cdiv(N_NODES, 8), TB>>>();
    coef_k<8><<<cdiv(ET * 8, TB), TB>>>();
    agg_k<8, 32><<<cdiv(N_NODES * 2 * 32, TB), TB>>>(xl, b1, x1, 256, 0);

    // dense gg path -> xf0[:, 0:32]
    gemm_k<<<gemm_grid(32), TB>>>(x,   ln1_w, ln1_b, t32, N_NODES, 16, 32, 1, 32, 0);
    gemm_k<<<gemm_grid(32), TB>>>(t32, ln2_w, ln2_b, xf0, N_NODES, 32, 32, 1, 1080, 0);

    // ---- conv2: 256 -> 8x32 -> x2 ----
    gemm_k<<<gemm_grid(256), TB>>>(x1, W2, nullptr, xl, N_NODES, 256, 256, 0, 256, 0);
    alpha_k<8, 32><<<cdiv(N_NODES * 8 * 32, TB), TB>>>(xl, as2, ad2);
    stats_k<8><<<cdiv(N_NODES, 8), TB>>>();
    coef_k<8><<<cdiv(ET * 8, TB), TB>>>();
    agg_k<8, 32><<<cdiv(N_NODES * 2 * 32, TB), TB>>>(xl, b2, x2, 256, 0);

    // ---- conv3: 256 -> 12x64 -> xf0[:, 32:800] ----
    gemm_k<<<gemm_grid(768), TB>>>(x2, W3, nullptr, xl, N_NODES, 256, 768, 0, 768, 0);
    alpha_k<12, 64><<<cdiv(N_NODES * 12 * 32, TB), TB>>>(xl, as3, ad3);
    stats_k<12><<<cdiv(N_NODES, 8), TB>>>();
    coef_k<12><<<cdiv(ET * 12, TB), TB>>>();
    agg_k<12, 64><<<cdiv(N_NODES * 6 * 32, TB), TB>>>(xl, b3, xf0, 1080, 32);

    // side dense paths -> xf0[:, 800:880], xf0[:, 880:1080]
    gemm_k<<<gemm_grid(80),  TB>>>(x1, la1_w, la1_b, xf0, N_NODES, 256, 80, 1, 1080, 800);
    gemm_k<<<gemm_grid(200), TB>>>(x2, la3_w, la3_b, xf0, N_NODES, 256, 200, 1, 1080, 880);

    // MLP head
    gemm_k<<<gemm_grid(200), TB>>>(xf0, lf1_w, lf1_b, xf1, N_NODES, 1080, 200, 1, 200, 0);
    gemm_k<<<gemm_grid(64),  TB>>>(xf1, lf2_w, lf2_b, xf2, N_NODES, 200, 64, 1, 64, 0);
    final_k<<<cdiv(N_NODES * 32, TB), TB>>>(xf2, lf3_w, lf3_b, out);
}

// round 9
// speedup vs baseline: 2.5442x; 1.0857x over previous
#include <cuda_runtime.h>
#include <mma.h>
#include <math.h>

using namespace nvcuda;

#define N_NODES 50000
#define N_EDGES 400000
#define ET (N_EDGES + N_NODES)   // 450000 edges incl. self-loops
#define TB 256
#define SCAN_B 1024
#define SCAN_G ((N_NODES + SCAN_B - 1) / SCAN_B)   // 49

// ---------------- scratch (device globals; no allocs allowed) ----------------
__device__ float g_xl [(size_t)N_NODES * 768];
__device__ float g_x1 [(size_t)N_NODES * 256];
__device__ float g_x2 [(size_t)N_NODES * 256];
__device__ float g_t32[(size_t)N_NODES * 32];
__device__ float g_xf0[(size_t)N_NODES * 1080];  // [gg | conv3 | xa1 | xa2]
__device__ float g_xf1[(size_t)N_NODES * 200];
__device__ float g_xf2[(size_t)N_NODES * 64];
__device__ float g_als[(size_t)N_NODES * 12];
__device__ float g_ald[(size_t)N_NODES * 12];
__device__ float g_m  [(size_t)N_NODES * 12];    // per-dst softmax max
__device__ float g_den[(size_t)N_NODES * 12];    // per-dst 1/sum
__device__ int   g_src[ET];
__device__ int   g_dst[ET];
__device__ int   g_deg[N_NODES];
__device__ int   g_rs [N_NODES + 1];
__device__ int   g_cur[N_NODES];
__device__ int   g_csr[ET];                      // CSR slot -> src node
__device__ int   g_bsum[SCAN_G];
__device__ int   g_boff[SCAN_G];
__device__ int   g_is64;

// ---------------- dtype probe ------------------------------------------------
__global__ void detect_dtype_k(const int* __restrict__ ei32) {
    int all_zero = 1;
#pragma unroll
    for (int i = 0; i < 16; i++)
        if (ei32[2 * i + 1] != 0) all_zero = 0;
    g_is64 = all_zero;
}

__global__ void zero_deg_k() {
    int i = blockIdx.x * blockDim.x + threadIdx.x;
    if (i < N_NODES) g_deg[i] = 0;
}

__global__ void prep_edges_k(const void* __restrict__ ei) {
    int i = blockIdx.x * blockDim.x + threadIdx.x;
    if (i >= ET) return;
    int s, d;
    if (i < N_EDGES) {
        if (g_is64) {
            const long long* p = (const long long*)ei;
            s = (int)p[i]; d = (int)p[N_EDGES + i];
        } else {
            const int* p = (const int*)ei;
            s = p[i]; d = p[N_EDGES + i];
        }
    } else {
        s = d = i - N_EDGES;
    }
    g_src[i] = s;
    g_dst[i] = d;
    atomicAdd(&g_deg[d], 1);
}

// ---------------- deterministic 3-phase scan ----------------------------------
__global__ void scan1_k() {
    __shared__ int sh[SCAN_B];
    int b = blockIdx.x, t = threadIdx.x;
    int idx = b * SCAN_B + t;
    int v = (idx < N_NODES) ? g_deg[idx] : 0;
    sh[t] = v;
    __syncthreads();
    for (int o = 1; o < SCAN_B; o <<= 1) {
        int u = (t >= o) ? sh[t - o] : 0;
        __syncthreads();
        sh[t] += u;
        __syncthreads();
    }
    if (idx < N_NODES) g_rs[idx] = sh[t] - v;
    if (t == SCAN_B - 1) g_bsum[b] = sh[t];
}

__global__ void scan2_k() {
    if (threadIdx.x == 0) {
        int run = 0;
        for (int b = 0; b < SCAN_G; b++) { g_boff[b] = run; run += g_bsum[b]; }
    }
}

__global__ void scan3_k() {
    int idx = blockIdx.x * SCAN_B + threadIdx.x;
    if (idx < N_NODES) {
        int v = g_rs[idx] + g_boff[blockIdx.x];
        g_rs[idx] = v;
        g_cur[idx] = v;
    }
    if (idx == 0) g_rs[N_NODES] = ET;
}

__global__ void scatter_k() {
    int e = blockIdx.x * blockDim.x + threadIdx.x;
    if (e >= ET) return;
    int pos = atomicAdd(&g_cur[g_dst[e]], 1);
    g_csr[pos] = g_src[e];
}

// ---------------- TF32 tensor-core GEMM, cp.async double-buffered -------------
#define BM 128
#define BN 64
#define BK 16

__device__ __forceinline__ void cpa16(float* dst, const float* src, bool valid) {
    unsigned d = (unsigned)__cvta_generic_to_shared(dst);
    int sz = valid ? 16 : 0;
    asm volatile("cp.async.ca.shared.global [%0], [%1], 16, %2;\n"
                 :: "r"(d), "l"(src), "r"(sz));
}

// All call sites guarantee K%4==0, colOff%4==0, ldC%4==0 (vectorized epilogue).
__global__ void gemm_k(const float* __restrict__ A, const float* __restrict__ B,
                       const float* __restrict__ bias, float* __restrict__ C,
                       int Nr, int M, int K, int act, int ldC, int colOff) {
    __shared__ __align__(16) unsigned char smem_raw[34816];
    float* As = (float*)smem_raw;                         // [2][128][16]
    float* Bs = (float*)(smem_raw + 16384);               // [2][16][72]
    float* Cs = (float*)smem_raw;                         // [128][68]
    int tid = threadIdx.x;
    int wid = tid >> 5;
    int wm = wid >> 1;
    int wn = wid & 1;
    int rowBase = blockIdx.y * BM;
    int colBase = blockIdx.x * BN;

    wmma::fragment<wmma::accumulator, 16, 16, 8, float> acc[2][2];
#pragma unroll
    for (int i = 0; i < 2; i++)
#pragma unroll
        for (int j = 0; j < 2; j++) wmma::fill_fragment(acc[i][j], 0.f);

    int nt = (M + BK - 1) / BK;

    auto load_tile = [&](int k0, int buf) {
        for (int i = tid; i < 512; i += 256) {
            int r = i >> 2, c4 = i & 3;
            int gr = rowBase + r, gk = k0 + c4 * 4;
            bool v = (gr < Nr) && (gk + 4 <= M);
            const float* src = v ? (A + (size_t)gr * M + gk) : A;
            cpa16(As + buf * 2048 + r * 16 + c4 * 4, src, v);
        }
        {
            int r = tid >> 4, c4 = tid & 15;
            int gk = k0 + r, gc = colBase + c4 * 4;
            bool v = (gk < M) && (gc + 4 <= K);
            const float* src = v ? (B + (size_t)gk * K + gc) : B;
            cpa16(Bs + buf * 1152 + r * 72 + c4 * 4, src, v);
        }
        asm volatile("cp.async.commit_group;\n");
    };

    load_tile(0, 0);
    for (int t = 0; t < nt; t++) {
        if (t + 1 < nt) {
            load_tile((t + 1) * BK, (t + 1) & 1);
            asm volatile("cp.async.wait_group 1;\n");
        } else {
            asm volatile("cp.async.wait_group 0;\n");
        }
        __syncthreads();
        int buf = t & 1;
        float* Ab = As + buf * 2048;
        float* Bb = Bs + buf * 1152;
#pragma unroll
        for (int ks = 0; ks < 2; ks++) {
            wmma::fragment<wmma::matrix_a, 16, 16, 8, wmma::precision::tf32, wmma::row_major> af[2];
            wmma::fragment<wmma::matrix_b, 16, 16, 8, wmma::precision::tf32, wmma::row_major> bf[2];
#pragma unroll
            for (int i = 0; i < 2; i++) {
                wmma::load_matrix_sync(af[i], Ab + (wm * 32 + i * 16) * 16 + ks * 8, BK);
#pragma unroll
                for (int e = 0; e < af[i].num_elements; e++)
                    af[i].x[e] = wmma::__float_to_tf32(af[i].x[e]);
            }
#pragma unroll
            for (int j = 0; j < 2; j++) {
                wmma::load_matrix_sync(bf[j], Bb + (ks * 8) * 72 + wn * 32 + j * 16, 72);
#pragma unroll
                for (int e = 0; e < bf[j].num_elements; e++)
                    bf[j].x[e] = wmma::__float_to_tf32(bf[j].x[e]);
            }
#pragma unroll
            for (int i = 0; i < 2; i++)
#pragma unroll
                for (int j = 0; j < 2; j++)
                    wmma::mma_sync(acc[i][j], af[i], bf[j], acc[i][j]);
        }
        __syncthreads();
    }

    // epilogue: stage accumulators into (aliased) Cs, then float4 global write
#pragma unroll
    for (int i = 0; i < 2; i++)
#pragma unroll
        for (int j = 0; j < 2; j++)
            wmma::store_matrix_sync(Cs + (wm * 32 + i * 16) * 68 + wn * 32 + j * 16,
                                    acc[i][j], 68, wmma::mem_row_major);
    __syncthreads();
    for (int i = tid; i < BM * BN / 4; i += 256) {
        int r = i >> 4;
        int c4 = (i & 15) << 2;
        int gr = rowBase + r, gc = colBase + c4;
        if (gr >= Nr || gc >= K) continue;     // K%4==0 -> gc<K implies gc+4<=K
        float4 v = *(const float4*)(Cs + r * 68 + c4);
        if (bias) {
            float4 bb = *(const float4*)(bias + gc);
            v.x += bb.x; v.y += bb.y; v.z += bb.z; v.w += bb.w;
        }
        if (act) {
            v.x = fmaxf(v.x, 0.f); v.y = fmaxf(v.y, 0.f);
            v.z = fmaxf(v.z, 0.f); v.w = fmaxf(v.w, 0.f);
        }
        *(float4*)(C + (size_t)gr * ldC + colOff + gc) = v;
    }
}

// ---------------- per-node attention logits: warp per (n,h) -------------------
template <int H, int C>
__global__ void alpha_k(const float* __restrict__ xl,
                        const float* __restrict__ a_src,
                        const float* __restrict__ a_dst) {
    int gw = (blockIdx.x * blockDim.x + threadIdx.x) >> 5;
    int lane = threadIdx.x & 31;
    if (gw >= N_NODES * H) return;
    int n = gw / H, h = gw - n * H;
    const float* row = xl + (size_t)n * (H * C) + h * C;
    float s1 = 0.f, s2 = 0.f;
#pragma unroll
    for (int c = lane; c < C; c += 32) {
        float v = row[c];
        s1 += v * a_src[h * C + c];
        s2 += v * a_dst[h * C + c];
    }
#pragma unroll
    for (int o = 16; o; o >>= 1) {
        s1 += __shfl_down_sync(0xffffffffu, s1, o);
        s2 += __shfl_down_sync(0xffffffffu, s2, o);
    }
    if (lane == 0) { g_als[gw] = s1; g_ald[gw] = s2; }
}

__device__ __forceinline__ float lrelu(float v) { return v > 0.f ? v : 0.2f * v; }

// ---------------- stats: per-dst online softmax (m, 1/den) --------------------
template <int H>
__global__ void stats_k() {
    int wid = threadIdx.x >> 5, lane = threadIdx.x & 31;
    int d = blockIdx.x * 8 + wid;
    if (d >= N_NODES) return;
    int beg = g_rs[d], end = g_rs[d + 1];
    float aldv[H];
#pragma unroll
    for (int h = 0; h < H; h++) aldv[h] = g_ald[d * H + h];
    float m[H], s[H];
#pragma unroll
    for (int h = 0; h < H; h++) { m[h] = -1e30f; s[h] = 0.f; }
    for (int j = beg + lane; j < end; j += 32) {
        int src = g_csr[j];
#pragma unroll
        for (int h = 0; h < H; h++) {
            float v = lrelu(g_als[src * H + h] + aldv[h]);
            if (v > m[h]) { s[h] = s[h] * __expf(m[h] - v) + 1.f; m[h] = v; }
            else          { s[h] += __expf(v - m[h]); }
        }
    }
#pragma unroll
    for (int h = 0; h < H; h++) {
#pragma unroll
        for (int o = 16; o; o >>= 1) {
            float mo = __shfl_xor_sync(0xffffffffu, m[h], o);
            float so = __shfl_xor_sync(0xffffffffu, s[h], o);
            float M = fmaxf(m[h], mo);
            s[h] = s[h] * __expf(m[h] - M) + so * __expf(mo - M);
            m[h] = M;
        }
    }
    if (lane == 0) {
#pragma unroll
        for (int h = 0; h < H; h++) {
            g_m[d * H + h] = m[h];
            g_den[d * H + h] = 1.f / s[h];
        }
    }
}

// ---------------- agg: warp per (dst, 128-float chunk), coef inline -----------
template <int H, int C>
__global__ void agg_k(const float* __restrict__ xl, const float* __restrict__ bias,
                      float* __restrict__ out, int ldo, int colOff) {
    const int HC = H * C;
    const int CH = HC / 128;
    int w = (blockIdx.x * blockDim.x + threadIdx.x) >> 5;
    int lane = threadIdx.x & 31;
    if (w >= N_NODES * CH) return;
    int d = w / CH, c = w - d * CH;
    int beg = g_rs[d], end = g_rs[d + 1];
    int col = c * 128 + lane * 4;
    int hm = col / C;
    float ald  = g_ald[d * H + hm];
    float mref = g_m  [d * H + hm];
    float rden = g_den[d * H + hm];
    const float4* xbase = (const float4*)xl + (col >> 2);
    float4 acc = make_float4(0.f, 0.f, 0.f, 0.f);
    for (int j = beg; j < end; j++) {
        int src = g_csr[j];
        float v = lrelu(g_als[src * H + hm] + ald);
        float coef = __expf(v - mref) * rden;
        float4 xv = xbase[(size_t)src * (HC / 4)];
        acc.x += coef * xv.x; acc.y += coef * xv.y;
        acc.z += coef * xv.z; acc.w += coef * xv.w;
    }
    float4 bb = *(const float4*)(bias + col);
    float4 r;
    r.x = fmaxf(acc.x + bb.x, 0.f);
    r.y = fmaxf(acc.y + bb.y, 0.f);
    r.z = fmaxf(acc.z + bb.z, 0.f);
    r.w = fmaxf(acc.w + bb.w, 0.f);
    *(float4*)(out + (size_t)d * ldo + colOff + col) = r;
}

// ---------------- final: sigmoid(dot(xf2[n,:64], w) + b) ----------------------
__global__ void final_k(const float* __restrict__ xf2, const float* __restrict__ w,
                        const float* __restrict__ b, float* __restrict__ out) {
    int gw = (blockIdx.x * blockDim.x + threadIdx.x) >> 5;
    int lane = threadIdx.x & 31;
    if (gw >= N_NODES) return;
    const float* r = xf2 + (size_t)gw * 64;
    float s = r[lane] * w[lane] + r[lane + 32] * w[lane + 32];
#pragma unroll
    for (int o = 16; o; o >>= 1) s += __shfl_down_sync(0xffffffffu, s, o);
    if (lane == 0) out[gw] = 1.f / (1.f + expf(-(s + b[0])));
}

// =============================================================================
static inline dim3 gemm_grid(int K) { return dim3((K + BN - 1) / BN, (N_NODES + BM - 1) / BM); }
static inline int cdiv(int a, int b) { return (a + b - 1) / b; }

extern "C" void kernel_launch(void* const* d_in, const int* in_sizes, int n_in,
                              void* d_out, int out_size) {
    const float* x  = (const float*)d_in[0];
    const void*  ei = d_in[1];
    const float *W1 = (const float*)d_in[2],  *as1 = (const float*)d_in[3],
                *ad1 = (const float*)d_in[4], *b1  = (const float*)d_in[5];
    const float *W2 = (const float*)d_in[6],  *as2 = (const float*)d_in[7],
                *ad2 = (const float*)d_in[8], *b2  = (const float*)d_in[9];
    const float *W3 = (const float*)d_in[10], *as3 = (const float*)d_in[11],
                *ad3 = (const float*)d_in[12], *b3 = (const float*)d_in[13];
    const float *ln1_w = (const float*)d_in[14], *ln1_b = (const float*)d_in[15];
    const float *ln2_w = (const float*)d_in[16], *ln2_b = (const float*)d_in[17];
    const float *la1_w = (const float*)d_in[18], *la1_b = (const float*)d_in[19];
    const float *la3_w = (const float*)d_in[20], *la3_b = (const float*)d_in[21];
    const float *lf1_w = (const float*)d_in[22], *lf1_b = (const float*)d_in[23];
    const float *lf2_w = (const float*)d_in[24], *lf2_b = (const float*)d_in[25];
    const float *lf3_w = (const float*)d_in[26], *lf3_b = (const float*)d_in[27];
    float* out = (float*)d_out;

    float *xl, *x1, *x2, *t32, *xf0, *xf1, *xf2;
    cudaGetSymbolAddress((void**)&xl,  g_xl);
    cudaGetSymbolAddress((void**)&x1,  g_x1);
    cudaGetSymbolAddress((void**)&x2,  g_x2);
    cudaGetSymbolAddress((void**)&t32, g_t32);
    cudaGetSymbolAddress((void**)&xf0, g_xf0);
    cudaGetSymbolAddress((void**)&xf1, g_xf1);
    cudaGetSymbolAddress((void**)&xf2, g_xf2);

    // edge prep
    detect_dtype_k<<<1, 1>>>((const int*)ei);
    zero_deg_k<<<cdiv(N_NODES, TB), TB>>>();
    prep_edges_k<<<cdiv(ET, TB), TB>>>(ei);
    gemm_k<<<gemm_grid(256), TB>>>(x, W1, nullptr, xl, N_NODES, 16, 256, 0, 256, 0);
    scan1_k<<<SCAN_G, SCAN_B>>>();
    scan2_k<<<1, 32>>>();
    scan3_k<<<SCAN_G, SCAN_B>>>();
    scatter_k<<<cdiv(ET, TB), TB>>>();

    // ---- conv1: 16 -> 8x32 -> x1 ----
    alpha_k<8, 32><<<cdiv(N_NODES * 8 * 32, TB), TB>>>(xl, as1, ad1);
    stats_k<8><<<cdiv(N_NODES, 8), TB>>>();
    agg_k<8, 32><<<cdiv(N_NODES * 2 * 32, TB), TB>>>(xl, b1, x1, 256, 0);

    // dense gg path -> xf0[:, 0:32]
    gemm_k<<<gemm_grid(32), TB>>>(x,   ln1_w, ln1_b, t32, N_NODES, 16, 32, 1, 32, 0);
    gemm_k<<<gemm_grid(32), TB>>>(t32, ln2_w, ln2_b, xf0, N_NODES, 32, 32, 1, 1080, 0);

    // ---- conv2: 256 -> 8x32 -> x2 ----
    gemm_k<<<gemm_grid(256), TB>>>(x1, W2, nullptr, xl, N_NODES, 256, 256, 0, 256, 0);
    alpha_k<8, 32><<<cdiv(N_NODES * 8 * 32, TB), TB>>>(xl, as2, ad2);
    stats_k<8><<<cdiv(N_NODES, 8), TB>>>();
    agg_k<8, 32><<<cdiv(N_NODES * 2 * 32, TB), TB>>>(xl, b2, x2, 256, 0);

    // ---- conv3: 256 -> 12x64 -> xf0[:, 32:800] ----
    gemm_k<<<gemm_grid(768), TB>>>(x2, W3, nullptr, xl, N_NODES, 256, 768, 0, 768, 0);
    alpha_k<12, 64><<<cdiv(N_NODES * 12 * 32, TB), TB>>>(xl, as3, ad3);
    stats_k<12><<<cdiv(N_NODES, 8), TB>>>();
    agg_k<12, 64><<<cdiv(N_NODES * 6 * 32, TB), TB>>>(xl, b3, xf0, 1080, 32);

    // side dense paths -> xf0[:, 800:880], xf0[:, 880:1080]
    gemm_k<<<gemm_grid(80),  TB>>>(x1, la1_w, la1_b, xf0, N_NODES, 256, 80, 1, 1080, 800);
    gemm_k<<<gemm_grid(200), TB>>>(x2, la3_w, la3_b, xf0, N_NODES, 256, 200, 1, 1080, 880);

    // MLP head
    gemm_k<<<gemm_grid(200), TB>>>(xf0, lf1_w, lf1_b, xf1, N_NODES, 1080, 200, 1, 200, 0);
    gemm_k<<<gemm_grid(64),  TB>>>(xf1, lf2_w, lf2_b, xf2, N_NODES, 200, 64, 1, 64, 0);
    final_k<<<cdiv(N_NODES * 32, TB), TB>>>(xf2, lf3_w, lf3_b, out);
}

// round 11
// speedup vs baseline: 2.7540x; 1.0824x over previous
#include <cuda_runtime.h>
#include <mma.h>
#include <math.h>

using namespace nvcuda;

#define N_NODES 50000
#define N_EDGES 400000
#define ET (N_EDGES + N_NODES)   // 450000 edges incl. self-loops
#define TB 256
#define SCAN_B 1024
#define SCAN_G ((N_NODES + SCAN_B - 1) / SCAN_B)   // 49

// ---------------- scratch (device globals; no allocs allowed) ----------------
__device__ float g_xl [(size_t)N_NODES * 768];
__device__ float g_x1 [(size_t)N_NODES * 256];
__device__ float g_x2 [(size_t)N_NODES * 256];
__device__ float g_t32[(size_t)N_NODES * 32];
__device__ float g_xf0[(size_t)N_NODES * 1080];  // [gg | conv3 | xa1 | xa2]
__device__ float g_xf1[(size_t)N_NODES * 200];
__device__ float g_xf2[(size_t)N_NODES * 64];
__device__ float g_als[(size_t)N_NODES * 12];
__device__ float g_ald[(size_t)N_NODES * 12];
__device__ float g_m  [(size_t)N_NODES * 12];    // per-dst softmax max
__device__ float g_den[(size_t)N_NODES * 12];    // per-dst 1/sum
__device__ int   g_src[ET];
__device__ int   g_dst[ET];
__device__ int   g_deg[N_NODES];
__device__ int   g_rs [N_NODES + 1];
__device__ int   g_cur[N_NODES];
__device__ int   g_csr[ET];                      // CSR slot -> src node
__device__ int   g_bsum[SCAN_G];
__device__ int   g_boff[SCAN_G];
__device__ int   g_is64;

// ---------------- dtype probe ------------------------------------------------
__global__ void detect_dtype_k(const int* __restrict__ ei32) {
    int all_zero = 1;
#pragma unroll
    for (int i = 0; i < 16; i++)
        if (ei32[2 * i + 1] != 0) all_zero = 0;
    g_is64 = all_zero;
}

__global__ void zero_deg_k() {
    int i = blockIdx.x * blockDim.x + threadIdx.x;
    if (i < N_NODES) g_deg[i] = 0;
}

__global__ void prep_edges_k(const void* __restrict__ ei) {
    int i = blockIdx.x * blockDim.x + threadIdx.x;
    if (i >= ET) return;
    int s, d;
    if (i < N_EDGES) {
        if (g_is64) {
            const long long* p = (const long long*)ei;
            s = (int)p[i]; d = (int)p[N_EDGES + i];
        } else {
            const int* p = (const int*)ei;
            s = p[i]; d = p[N_EDGES + i];
        }
    } else {
        s = d = i - N_EDGES;
    }
    g_src[i] = s;
    g_dst[i] = d;
    atomicAdd(&g_deg[d], 1);
}

// ---------------- deterministic 3-phase scan ----------------------------------
__global__ void scan1_k() {
    __shared__ int sh[SCAN_B];
    int b = blockIdx.x, t = threadIdx.x;
    int idx = b * SCAN_B + t;
    int v = (idx < N_NODES) ? g_deg[idx] : 0;
    sh[t] = v;
    __syncthreads();
    for (int o = 1; o < SCAN_B; o <<= 1) {
        int u = (t >= o) ? sh[t - o] : 0;
        __syncthreads();
        sh[t] += u;
        __syncthreads();
    }
    if (idx < N_NODES) g_rs[idx] = sh[t] - v;
    if (t == SCAN_B - 1) g_bsum[b] = sh[t];
}

__global__ void scan2_k() {
    if (threadIdx.x == 0) {
        int run = 0;
        for (int b = 0; b < SCAN_G; b++) { g_boff[b] = run; run += g_bsum[b]; }
    }
}

__global__ void scan3_k() {
    int idx = blockIdx.x * SCAN_B + threadIdx.x;
    if (idx < N_NODES) {
        int v = g_rs[idx] + g_boff[blockIdx.x];
        g_rs[idx] = v;
        g_cur[idx] = v;
    }
    if (idx == 0) g_rs[N_NODES] = ET;
}

__global__ void scatter_k() {
    int e = blockIdx.x * blockDim.x + threadIdx.x;
    if (e >= ET) return;
    int pos = atomicAdd(&g_cur[g_dst[e]], 1);
    g_csr[pos] = g_src[e];
}

// ---------------- TF32 tensor-core GEMM, cp.async double-buffered, BK=32 ------
// Dynamic smem (55296 B > 48 KB static limit): [2][128][36]A | [2][32][72]B,
// epilogue Cs[128][68] aliases the stage region.
#define BM 128
#define BN 64
#define BK 32
#define A_LD 36
#define B_LD 72
#define A_STG (BM * A_LD)          // floats per A stage  = 4608
#define B_STG (BK * B_LD)          // floats per B stage  = 2304
#define GEMM_SMEM ((2 * A_STG + 2 * B_STG) * 4)   // 55296 bytes

__device__ __forceinline__ void cpa16(float* dst, const float* src, bool valid) {
    unsigned d = (unsigned)__cvta_generic_to_shared(dst);
    int sz = valid ? 16 : 0;                 // src-size 0 => zero-fill 16B
    asm volatile("cp.async.ca.shared.global [%0], [%1], 16, %2;\n"
                 :: "r"(d), "l"(src), "r"(sz));
}

// All call sites guarantee K%4==0, colOff%4==0, ldC%4==0 (vectorized epilogue).
// NOTE: no explicit fp32->tf32 rounding; HMMA truncates mantissa (ok @1e-3 gate).
__global__ void gemm_k(const float* __restrict__ A, const float* __restrict__ B,
                       const float* __restrict__ bias, float* __restrict__ C,
                       int Nr, int M, int K, int act, int ldC, int colOff) {
    extern __shared__ __align__(16) float smem_dyn[];
    float* As = smem_dyn;                     // [2][128][36]
    float* Bs = smem_dyn + 2 * A_STG;         // [2][32][72]
    float* Cs = smem_dyn;                     // [128][68] (aliases stages)
    int tid = threadIdx.x;
    int wid = tid >> 5;
    int wm = wid >> 1;
    int wn = wid & 1;
    int rowBase = blockIdx.y * BM;
    int colBase = blockIdx.x * BN;

    wmma::fragment<wmma::accumulator, 16, 16, 8, float> acc[2][2];
#pragma unroll
    for (int i = 0; i < 2; i++)
#pragma unroll
        for (int j = 0; j < 2; j++) wmma::fill_fragment(acc[i][j], 0.f);

    int nt = (M + BK - 1) / BK;

    auto load_tile = [&](int k0, int buf) {
        // A: 128 rows x 8 float4 = 1024 float4
#pragma unroll
        for (int i = tid; i < 1024; i += 256) {
            int r = i >> 3, c4 = i & 7;
            int gr = rowBase + r, gk = k0 + c4 * 4;
            bool v = (gr < Nr) && (gk + 4 <= M);
            const float* src = v ? (A + (size_t)gr * M + gk) : A;
            cpa16(As + buf * A_STG + r * A_LD + c4 * 4, src, v);
        }
        // B: 32 rows x 16 float4 = 512 float4
#pragma unroll
        for (int i = tid; i < 512; i += 256) {
            int r = i >> 4, c4 = i & 15;
            int gk = k0 + r, gc = colBase + c4 * 4;
            bool v = (gk < M) && (gc + 4 <= K);
            const float* src = v ? (B + (size_t)gk * K + gc) : B;
            cpa16(Bs + buf * B_STG + r * B_LD + c4 * 4, src, v);
        }
        asm volatile("cp.async.commit_group;\n");
    };

    load_tile(0, 0);
    for (int t = 0; t < nt; t++) {
        if (t + 1 < nt) {
            load_tile((t + 1) * BK, (t + 1) & 1);
            asm volatile("cp.async.wait_group 1;\n");
        } else {
            asm volatile("cp.async.wait_group 0;\n");
        }
        __syncthreads();
        int buf = t & 1;
        float* Ab = As + buf * A_STG;
        float* Bb = Bs + buf * B_STG;
#pragma unroll
        for (int ks = 0; ks < 4; ks++) {
            wmma::fragment<wmma::matrix_a, 16, 16, 8, wmma::precision::tf32, wmma::row_major> af[2];
            wmma::fragment<wmma::matrix_b, 16, 16, 8, wmma::precision::tf32, wmma::row_major> bf[2];
#pragma unroll
            for (int i = 0; i < 2; i++)
                wmma::load_matrix_sync(af[i], Ab + (wm * 32 + i * 16) * A_LD + ks * 8, A_LD);
#pragma unroll
            for (int j = 0; j < 2; j++)
                wmma::load_matrix_sync(bf[j], Bb + (ks * 8) * B_LD + wn * 32 + j * 16, B_LD);
#pragma unroll
            for (int i = 0; i < 2; i++)
#pragma unroll
                for (int j = 0; j < 2; j++)
                    wmma::mma_sync(acc[i][j], af[i], bf[j], acc[i][j]);
        }
        __syncthreads();
    }

    // epilogue: stage accumulators into (aliased) Cs, then float4 global write
#pragma unroll
    for (int i = 0; i < 2; i++)
#pragma unroll
        for (int j = 0; j < 2; j++)
            wmma::store_matrix_sync(Cs + (wm * 32 + i * 16) * 68 + wn * 32 + j * 16,
                                    acc[i][j], 68, wmma::mem_row_major);
    __syncthreads();
    for (int i = tid; i < BM * BN / 4; i += 256) {
        int r = i >> 4;
        int c4 = (i & 15) << 2;
        int gr = rowBase + r, gc = colBase + c4;
        if (gr >= Nr || gc >= K) continue;     // K%4==0 -> gc<K implies gc+4<=K
        float4 v = *(const float4*)(Cs + r * 68 + c4);
        if (bias) {
            float4 bb = *(const float4*)(bias + gc);
            v.x += bb.x; v.y += bb.y; v.z += bb.z; v.w += bb.w;
        }
        if (act) {
            v.x = fmaxf(v.x, 0.f); v.y = fmaxf(v.y, 0.f);
            v.z = fmaxf(v.z, 0.f); v.w = fmaxf(v.w, 0.f);
        }
        *(float4*)(C + (size_t)gr * ldC + colOff + gc) = v;
    }
}

// ---------------- per-node attention logits: warp per (n,h) -------------------
template <int H, int C>
__global__ void alpha_k(const float* __restrict__ xl,
                        const float* __restrict__ a_src,
                        const float* __restrict__ a_dst) {
    int gw = (blockIdx.x * blockDim.x + threadIdx.x) >> 5;
    int lane = threadIdx.x & 31;
    if (gw >= N_NODES * H) return;
    int n = gw / H, h = gw - n * H;
    const float* row = xl + (size_t)n * (H * C) + h * C;
    float s1 = 0.f, s2 = 0.f;
#pragma unroll
    for (int c = lane; c < C; c += 32) {
        float v = row[c];
        s1 += v * a_src[h * C + c];
        s2 += v * a_dst[h * C + c];
    }
#pragma unroll
    for (int o = 16; o; o >>= 1) {
        s1 += __shfl_down_sync(0xffffffffu, s1, o);
        s2 += __shfl_down_sync(0xffffffffu, s2, o);
    }
    if (lane == 0) { g_als[gw] = s1; g_ald[gw] = s2; }
}

__device__ __forceinline__ float lrelu(float v) { return v > 0.f ? v : 0.2f * v; }

// ---------------- stats: per-dst online softmax (m, 1/den) --------------------
template <int H>
__global__ void stats_k() {
    int wid = threadIdx.x >> 5, lane = threadIdx.x & 31;
    int d = blockIdx.x * 8 + wid;
    if (d >= N_NODES) return;
    int beg = g_rs[d], end = g_rs[d + 1];
    float aldv[H];
#pragma unroll
    for (int h = 0; h < H; h++) aldv[h] = g_ald[d * H + h];
    float m[H], s[H];
#pragma unroll
    for (int h = 0; h < H; h++) { m[h] = -1e30f; s[h] = 0.f; }
    for (int j = beg + lane; j < end; j += 32) {
        int src = g_csr[j];
#pragma unroll
        for (int h = 0; h < H; h++) {
            float v = lrelu(g_als[src * H + h] + aldv[h]);
            if (v > m[h]) { s[h] = s[h] * __expf(m[h] - v) + 1.f; m[h] = v; }
            else          { s[h] += __expf(v - m[h]); }
        }
    }
#pragma unroll
    for (int h = 0; h < H; h++) {
#pragma unroll
        for (int o = 16; o; o >>= 1) {
            float mo = __shfl_xor_sync(0xffffffffu, m[h], o);
            float so = __shfl_xor_sync(0xffffffffu, s[h], o);
            float M = fmaxf(m[h], mo);
            s[h] = s[h] * __expf(m[h] - M) + so * __expf(mo - M);
            m[h] = M;
        }
    }
    if (lane == 0) {
#pragma unroll
        for (int h = 0; h < H; h++) {
            g_m[d * H + h] = m[h];
            g_den[d * H + h] = 1.f / s[h];
        }
    }
}

// ---------------- agg: warp per (dst, 128-float chunk), coef inline -----------
template <int H, int C>
__global__ void agg_k(const float* __restrict__ xl, const float* __restrict__ bias,
                      float* __restrict__ out, int ldo, int colOff) {
    const int HC = H * C;
    const int CH = HC / 128;
    int w = (blockIdx.x * blockDim.x + threadIdx.x) >> 5;
    int lane = threadIdx.x & 31;
    if (w >= N_NODES * CH) return;
    int d = w / CH, c = w - d * CH;
    int beg = g_rs[d], end = g_rs[d + 1];
    int col = c * 128 + lane * 4;
    int hm = col / C;
    float ald  = g_ald[d * H + hm];
    float mref = g_m  [d * H + hm];
    float rden = g_den[d * H + hm];
    const float4* xbase = (const float4*)xl + (col >> 2);
    float4 acc = make_float4(0.f, 0.f, 0.f, 0.f);
    for (int j = beg; j < end; j++) {
        int src = g_csr[j];
        float v = lrelu(g_als[src * H + hm] + ald);
        float coef = __expf(v - mref) * rden;
        float4 xv = xbase[(size_t)src * (HC / 4)];
        acc.x += coef * xv.x; acc.y += coef * xv.y;
        acc.z += coef * xv.z; acc.w += coef * xv.w;
    }
    float4 bb = *(const float4*)(bias + col);
    float4 r;
    r.x = fmaxf(acc.x + bb.x, 0.f);
    r.y = fmaxf(acc.y + bb.y, 0.f);
    r.z = fmaxf(acc.z + bb.z, 0.f);
    r.w = fmaxf(acc.w + bb.w, 0.f);
    *(float4*)(out + (size_t)d * ldo + colOff + col) = r;
}

// ---------------- final: sigmoid(dot(xf2[n,:64], w) + b) ----------------------
__global__ void final_k(const float* __restrict__ xf2, const float* __restrict__ w,
                        const float* __restrict__ b, float* __restrict__ out) {
    int gw = (blockIdx.x * blockDim.x + threadIdx.x) >> 5;
    int lane = threadIdx.x & 31;
    if (gw >= N_NODES) return;
    const float* r = xf2 + (size_t)gw * 64;
    float s = r[lane] * w[lane] + r[lane + 32] * w[lane + 32];
#pragma unroll
    for (int o = 16; o; o >>= 1) s += __shfl_down_sync(0xffffffffu, s, o);
    if (lane == 0) out[gw] = 1.f / (1.f + expf(-(s + b[0])));
}

// =============================================================================
static inline dim3 gemm_grid(int K) { return dim3((K + BN - 1) / BN, (N_NODES + BM - 1) / BM); }
static inline int cdiv(int a, int b) { return (a + b - 1) / b; }

extern "C" void kernel_launch(void* const* d_in, const int* in_sizes, int n_in,
                              void* d_out, int out_size) {
    const float* x  = (const float*)d_in[0];
    const void*  ei = d_in[1];
    const float *W1 = (const float*)d_in[2],  *as1 = (const float*)d_in[3],
                *ad1 = (const float*)d_in[4], *b1  = (const float*)d_in[5];
    const float *W2 = (const float*)d_in[6],  *as2 = (const float*)d_in[7],
                *ad2 = (const float*)d_in[8], *b2  = (const float*)d_in[9];
    const float *W3 = (const float*)d_in[10], *as3 = (const float*)d_in[11],
                *ad3 = (const float*)d_in[12], *b3 = (const float*)d_in[13];
    const float *ln1_w = (const float*)d_in[14], *ln1_b = (const float*)d_in[15];
    const float *ln2_w = (const float*)d_in[16], *ln2_b = (const float*)d_in[17];
    const float *la1_w = (const float*)d_in[18], *la1_b = (const float*)d_in[19];
    const float *la3_w = (const float*)d_in[20], *la3_b = (const float*)d_in[21];
    const float *lf1_w = (const float*)d_in[22], *lf1_b = (const float*)d_in[23];
    const float *lf2_w = (const float*)d_in[24], *lf2_b = (const float*)d_in[25];
    const float *lf3_w = (const float*)d_in[26], *lf3_b = (const float*)d_in[27];
    float* out = (float*)d_out;

    float *xl, *x1, *x2, *t32, *xf0, *xf1, *xf2;
    cudaGetSymbolAddress((void**)&xl,  g_xl);
    cudaGetSymbolAddress((void**)&x1,  g_x1);
    cudaGetSymbolAddress((void**)&x2,  g_x2);
    cudaGetSymbolAddress((void**)&t32, g_t32);
    cudaGetSymbolAddress((void**)&xf0, g_xf0);
    cudaGetSymbolAddress((void**)&xf1, g_xf1);
    cudaGetSymbolAddress((void**)&xf2, g_xf2);

    // allow >48KB dynamic smem for gemm_k (attribute set, not an allocation)
    cudaFuncSetAttribute(gemm_k, cudaFuncAttributeMaxDynamicSharedMemorySize, GEMM_SMEM);

    // edge prep
    detect_dtype_k<<<1, 1>>>((const int*)ei);
    zero_deg_k<<<cdiv(N_NODES, TB), TB>>>();
    prep_edges_k<<<cdiv(ET, TB), TB>>>(ei);
    gemm_k<<<gemm_grid(256), TB, GEMM_SMEM>>>(x, W1, nullptr, xl, N_NODES, 16, 256, 0, 256, 0);
    scan1_k<<<SCAN_G, SCAN_B>>>();
    scan2_k<<<1, 32>>>();
    scan3_k<<<SCAN_G, SCAN_B>>>();
    scatter_k<<<cdiv(ET, TB), TB>>>();

    // ---- conv1: 16 -> 8x32 -> x1 ----
    alpha_k<8, 32><<<cdiv(N_NODES * 8 * 32, TB), TB>>>(xl, as1, ad1);
    stats_k<8><<<cdiv(N_NODES, 8), TB>>>();
    agg_k<8, 32><<<cdiv(N_NODES * 2 * 32, TB), TB>>>(xl, b1, x1, 256, 0);

    // dense gg path -> xf0[:, 0:32]
    gemm_k<<<gemm_grid(32), TB, GEMM_SMEM>>>(x,   ln1_w, ln1_b, t32, N_NODES, 16, 32, 1, 32, 0);
    gemm_k<<<gemm_grid(32), TB, GEMM_SMEM>>>(t32, ln2_w, ln2_b, xf0, N_NODES, 32, 32, 1, 1080, 0);

    // ---- conv2: 256 -> 8x32 -> x2 ----
    gemm_k<<<gemm_grid(256), TB, GEMM_SMEM>>>(x1, W2, nullptr, xl, N_NODES, 256, 256, 0, 256, 0);
    alpha_k<8, 32><<<cdiv(N_NODES * 8 * 32, TB), TB>>>(xl, as2, ad2);
    stats_k<8><<<cdiv(N_NODES, 8), TB>>>();
    agg_k<8, 32><<<cdiv(N_NODES * 2 * 32, TB), TB>>>(xl, b2, x2, 256, 0);

    // ---- conv3: 256 -> 12x64 -> xf0[:, 32:800] ----
    gemm_k<<<gemm_grid(768), TB, GEMM_SMEM>>>(x2, W3, nullptr, xl, N_NODES, 256, 768, 0, 768, 0);
    alpha_k<12, 64><<<cdiv(N_NODES * 12 * 32, TB), TB>>>(xl, as3, ad3);
    stats_k<12><<<cdiv(N_NODES, 8), TB>>>();
    agg_k<12, 64><<<cdiv(N_NODES * 6 * 32, TB), TB>>>(xl, b3, xf0, 1080, 32);

    // side dense paths -> xf0[:, 800:880], xf0[:, 880:1080]
    gemm_k<<<gemm_grid(80),  TB, GEMM_SMEM>>>(x1, la1_w, la1_b, xf0, N_NODES, 256, 80, 1, 1080, 800);
    gemm_k<<<gemm_grid(200), TB, GEMM_SMEM>>>(x2, la3_w, la3_b, xf0, N_NODES, 256, 200, 1, 1080, 880);

    // MLP head
    gemm_k<<<gemm_grid(200), TB, GEMM_SMEM>>>(xf0, lf1_w, lf1_b, xf1, N_NODES, 1080, 200, 1, 200, 0);
    gemm_k<<<gemm_grid(64),  TB, GEMM_SMEM>>>(xf1, lf2_w, lf2_b, xf2, N_NODES, 200, 64, 1, 64, 0);
    final_k<<<cdiv(N_NODES * 32, TB), TB>>>(xf2, lf3_w, lf3_b, out);
}